// round 6
// baseline (speedup 1.0000x reference)
#include <cuda_runtime.h>
#include <cuda_bf16.h>
#include <cstdint>

#define BB 16
#define TT 2048
#define CC 512
#define HH 64
#define SCALE 0.125f

__device__ float g_q[BB * TT * HH];
__device__ float g_k[BB * TT * HH];
__device__ float g_v[BB * TT * HH];

// split x,y into packed bf16 hi pair and bf16 lo (residual) pair
__device__ __forceinline__ void pk(float x, float y, uint32_t& h, uint32_t& l) {
  __nv_bfloat16 hx = __float2bfloat16(x), hy = __float2bfloat16(y);
  float rx = x - __bfloat162float(hx), ry = y - __bfloat162float(hy);
  __nv_bfloat16 lx = __float2bfloat16(rx), ly = __float2bfloat16(ry);
  h = (uint32_t)__bfloat16_as_ushort(hx) |
      ((uint32_t)__bfloat16_as_ushort(hy) << 16);
  l = (uint32_t)__bfloat16_as_ushort(lx) |
      ((uint32_t)__bfloat16_as_ushort(ly) << 16);
}
__device__ __forceinline__ void pk1(float x, __nv_bfloat16& h,
                                    __nv_bfloat16& l) {
  h = __float2bfloat16(x);
  l = __float2bfloat16(x - __bfloat162float(h));
}

// m16n8k16 bf16 MMA, A row-major, B col-major, fp32 accum
__device__ __forceinline__ void mma16(float* c, uint32_t a0, uint32_t a1,
                                      uint32_t a2, uint32_t a3, uint32_t b0,
                                      uint32_t b1) {
  asm volatile(
      "mma.sync.aligned.m16n8k16.row.col.f32.bf16.bf16.f32 "
      "{%0,%1,%2,%3}, {%4,%5,%6,%7}, {%8,%9}, {%0,%1,%2,%3};"
      : "+f"(c[0]), "+f"(c[1]), "+f"(c[2]), "+f"(c[3])
      : "r"(a0), "r"(a1), "r"(a2), "r"(a3), "r"(b0), "r"(b1));
}
// bf16x2: hi*lo + lo*hi + hi*hi
__device__ __forceinline__ void mmax2(float* c, const uint32_t* ah,
                                      const uint32_t* al, uint32_t bh0,
                                      uint32_t bh1, uint32_t bl0,
                                      uint32_t bl1) {
  mma16(c, ah[0], ah[1], ah[2], ah[3], bl0, bl1);
  mma16(c, al[0], al[1], al[2], al[3], bh0, bh1);
  mma16(c, ah[0], ah[1], ah[2], ah[3], bh0, bh1);
}

// ---------------------------------------------------------------------------
// QKV projection, bf16x2 on m16n8k16. X tile A, W transposed (WT[n][k]) as B.
// ---------------------------------------------------------------------------
#define WXB 20  // words/row (40 bf16) for X tiles
#define WWB 20  // words/row for WT tiles
#define QKV_WORDS (2 * 64 * WXB + 2 * 192 * WWB)
__global__ __launch_bounds__(256) void qkv_mma(const float* __restrict__ x,
                                               const float* __restrict__ Wq,
                                               const float* __restrict__ Wk,
                                               const float* __restrict__ Wv) {
  extern __shared__ uint32_t qsm[];
  uint32_t* Xh = qsm;
  uint32_t* Xl = Xh + 64 * WXB;
  uint32_t* WTh = Xl + 64 * WXB;
  uint32_t* WTl = WTh + 192 * WWB;
  int tid = threadIdx.x, w = tid >> 5, lane = tid & 31;
  int g = lane >> 2, tg = lane & 3;
  int row0 = blockIdx.x * 64;
  int mt = w & 3, nh = w >> 2;
  float acc[12][4] = {};

  for (int k0 = 0; k0 < CC; k0 += 32) {
    __syncthreads();
    for (int i = tid; i < 512; i += 256) {  // X 64x32
      int r = i >> 3, h4 = (i & 7) << 2;
      float4 v4 = *(const float4*)&x[(size_t)(row0 + r) * CC + k0 + h4];
      uint32_t h01, l01, h23, l23;
      pk(v4.x, v4.y, h01, l01);
      pk(v4.z, v4.w, h23, l23);
      int wc = r * WXB + (h4 >> 1);
      *(uint2*)&Xh[wc] = make_uint2(h01, h23);
      *(uint2*)&Xl[wc] = make_uint2(l01, l23);
    }
    for (int i = tid; i < 1536; i += 256) {  // W 32x192 -> WT[n][k]
      int k = i / 48, n4 = (i % 48) * 4;
      int m = n4 >> 6, nn = n4 & 63;
      const float* Wm = m == 0 ? Wq : (m == 1 ? Wk : Wv);
      float4 v4 = *(const float4*)&Wm[(size_t)(k0 + k) * HH + nn];
      __nv_bfloat16* wth = (__nv_bfloat16*)WTh;
      __nv_bfloat16* wtl = (__nv_bfloat16*)WTl;
      __nv_bfloat16 hb, lb;
      pk1(v4.x, hb, lb);
      wth[(n4 + 0) * 2 * WWB + k] = hb;
      wtl[(n4 + 0) * 2 * WWB + k] = lb;
      pk1(v4.y, hb, lb);
      wth[(n4 + 1) * 2 * WWB + k] = hb;
      wtl[(n4 + 1) * 2 * WWB + k] = lb;
      pk1(v4.z, hb, lb);
      wth[(n4 + 2) * 2 * WWB + k] = hb;
      wtl[(n4 + 2) * 2 * WWB + k] = lb;
      pk1(v4.w, hb, lb);
      wth[(n4 + 3) * 2 * WWB + k] = hb;
      wtl[(n4 + 3) * 2 * WWB + k] = lb;
    }
    __syncthreads();
    int r1 = 16 * mt + g, r2 = r1 + 8;
#pragma unroll
    for (int c2 = 0; c2 < 2; c2++) {
      int kw = 8 * c2;
      uint32_t ah[4], al[4];
      ah[0] = Xh[r1 * WXB + kw + tg];
      ah[1] = Xh[r2 * WXB + kw + tg];
      ah[2] = Xh[r1 * WXB + kw + 4 + tg];
      ah[3] = Xh[r2 * WXB + kw + 4 + tg];
      al[0] = Xl[r1 * WXB + kw + tg];
      al[1] = Xl[r2 * WXB + kw + tg];
      al[2] = Xl[r1 * WXB + kw + 4 + tg];
      al[3] = Xl[r2 * WXB + kw + 4 + tg];
#pragma unroll
      for (int v = 0; v < 12; v++) {
        int n = 8 * (12 * nh + v) + g;
        uint32_t bh0 = WTh[n * WWB + kw + tg];
        uint32_t bh1 = WTh[n * WWB + kw + 4 + tg];
        uint32_t bl0 = WTl[n * WWB + kw + tg];
        uint32_t bl1 = WTl[n * WWB + kw + 4 + tg];
        mmax2(acc[v], ah, al, bh0, bh1, bl0, bl1);
      }
    }
  }
#pragma unroll
  for (int v = 0; v < 12; v++) {
    int ncol = 8 * (12 * nh + v) + 2 * tg;
    int m = ncol >> 6, nn = ncol & 63;
    float* o = m == 0 ? g_q : (m == 1 ? g_k : g_v);
    int r0 = row0 + 16 * mt + g;
    *(float2*)&o[(size_t)r0 * HH + nn] = make_float2(acc[v][0], acc[v][1]);
    *(float2*)&o[(size_t)(r0 + 8) * HH + nn] =
        make_float2(acc[v][2], acc[v][3]);
  }
}

// ---------------------------------------------------------------------------
// Fused attention, bf16x2 everywhere. Paired tiles (t0, T-64-t0) per CTA.
// Circular 96-slot Er band, V and P split at fill/softmax time.
// ---------------------------------------------------------------------------
#define WB 36  // words/row (72 bf16): Q,K,Qr,Er
#define WP 20  // words/row (40 bf16): P, Vt
#define PS 36
#define PG 104
#define ATTN_WORDS                                                      \
  (2 * 64 * WB + 4 * 32 * WB + 2 * 96 * WB + 2 * 64 * WP + 2 * 64 * WP + \
   64 * PS + 32 * PG + 4 * 64 + 512)

__global__ __launch_bounds__(256, 2) void attn_mma(
    const float* __restrict__ Er, float* __restrict__ out) {
  extern __shared__ uint32_t sm[];
  uint32_t* Qh = sm;
  uint32_t* Ql = Qh + 64 * WB;
  uint32_t* Kh = Ql + 64 * WB;
  uint32_t* Kl = Kh + 32 * WB;
  uint32_t* Qrh = Kl + 32 * WB;
  uint32_t* Qrl = Qrh + 32 * WB;
  uint32_t* Erh = Qrl + 32 * WB;
  uint32_t* Erl = Erh + 96 * WB;
  uint32_t* Vth = Erl + 96 * WB;  // [64 h][32 s] transposed
  uint32_t* Vtl = Vth + 64 * WP;
  uint32_t* Ph = Vtl + 64 * WP;
  uint32_t* Pl = Ph + 64 * WP;
  float* Ss = (float*)(Pl + 64 * WP);  // 64 x PS
  float* Gs = Ss + 64 * PS;            // 32 x PG
  float* ds = Gs + 32 * PG;
  float* ms = ds + 64;
  float* ls = ms + 64;
  float* as_ = ls + 64;
  float* pmax = as_ + 64;  // 4 x 64
  float* psum = pmax + 256;

  int tid = threadIdx.x, w = tid >> 5, lane = tid & 31;
  int g = lane >> 2, tg = lane & 3;
  int b = blockIdx.y;
  const float* Q = g_q + (size_t)b * TT * HH;
  const float* K = g_k + (size_t)b * TT * HH;
  const float* V = g_v + (size_t)b * TT * HH;

  int smt = w & 3, snh = w >> 2;
  int gmt = w & 1, gnb = w >> 1;
  int sr = tid & 63, sc = (tid >> 6) << 3;

  for (int half = 0; half < 2; half++) {
    int t0 = half == 0 ? blockIdx.x * 64 : (TT - 64 - blockIdx.x * 64);
    __syncthreads();
    for (int i = tid; i < 1024; i += 256) {  // Q tile 64x64
      int r = i >> 4, h4 = (i & 15) << 2;
      float4 v4 = *(const float4*)&Q[(size_t)(t0 + r) * HH + h4];
      uint32_t h01, l01, h23, l23;
      pk(v4.x, v4.y, h01, l01);
      pk(v4.z, v4.w, h23, l23);
      int wc = r * WB + (h4 >> 1);
      *(uint2*)&Qh[wc] = make_uint2(h01, h23);
      *(uint2*)&Ql[wc] = make_uint2(l01, l23);
    }
    __syncthreads();
    if (tid < 64) {
      const __nv_bfloat16* qh = (const __nv_bfloat16*)Qh + tid * 2 * WB;
      const __nv_bfloat16* ql = (const __nv_bfloat16*)Ql + tid * 2 * WB;
      const float* el = Er + (size_t)(TT - 1) * HH;
      float acc = 0.f;
#pragma unroll
      for (int h = 0; h < HH; h++)
        acc += (__bfloat162float(qh[h]) + __bfloat162float(ql[h])) * el[h];
      ds[tid] = acc;
      ms[tid] = -1e30f;
      ls[tid] = 0.f;
    }

    float O[4][4] = {};
    int niter = t0 / 32 + 2;

    for (int it = 0; it < niter; it++) {
      int s0 = it * 32;
      int rbase = t0 - s0 - 33;
      __syncthreads();
      for (int i = tid; i < 512; i += 256) {  // K, Vt, Qr tiles
        int r = i >> 4, h4 = (i & 15) << 2;
        int wc = r * WB + (h4 >> 1);
        uint32_t h01, l01, h23, l23;
        float4 kv = *(const float4*)&K[(size_t)(s0 + r) * HH + h4];
        pk(kv.x, kv.y, h01, l01);
        pk(kv.z, kv.w, h23, l23);
        *(uint2*)&Kh[wc] = make_uint2(h01, h23);
        *(uint2*)&Kl[wc] = make_uint2(l01, l23);
        float4 vv = *(const float4*)&V[(size_t)(s0 + r) * HH + h4];
        {  // transposed V: Vt[h][s]
          __nv_bfloat16* vth = (__nv_bfloat16*)Vth;
          __nv_bfloat16* vtl = (__nv_bfloat16*)Vtl;
          __nv_bfloat16 hb, lb;
          pk1(vv.x, hb, lb);
          vth[(h4 + 0) * 2 * WP + r] = hb;
          vtl[(h4 + 0) * 2 * WP + r] = lb;
          pk1(vv.y, hb, lb);
          vth[(h4 + 1) * 2 * WP + r] = hb;
          vtl[(h4 + 1) * 2 * WP + r] = lb;
          pk1(vv.z, hb, lb);
          vth[(h4 + 2) * 2 * WP + r] = hb;
          vtl[(h4 + 2) * 2 * WP + r] = lb;
          pk1(vv.w, hb, lb);
          vth[(h4 + 3) * 2 * WP + r] = hb;
          vtl[(h4 + 3) * 2 * WP + r] = lb;
        }
        int rq = s0 + 1 + r;
        if (rq > TT - 1) rq = TT - 1;  // clamped rows feed only masked slots
        float4 qv = *(const float4*)&Q[(size_t)rq * HH + h4];
        pk(qv.x, qv.y, h01, l01);
        pk(qv.z, qv.w, h23, l23);
        *(uint2*)&Qrh[wc] = make_uint2(h01, h23);
        *(uint2*)&Qrl[wc] = make_uint2(l01, l23);
      }
      {  // Er band: 96 slots first iter, 32 new rows after
        int nel = (it == 0 ? 96 : 32) * 16;
        for (int i = tid; i < nel; i += 256) {
          int xr = i >> 4, h4 = (i & 15) << 2;
          int r = rbase + xr;
          int slot = (r + 2112) % 96;
          int rc = r < 0 ? 0 : r;  // negative rows unused (masked)
          float4 ev = *(const float4*)&Er[(size_t)rc * HH + h4];
          uint32_t h01, l01, h23, l23;
          pk(ev.x, ev.y, h01, l01);
          pk(ev.z, ev.w, h23, l23);
          int wc = slot * WB + (h4 >> 1);
          *(uint2*)&Erh[wc] = make_uint2(h01, h23);
          *(uint2*)&Erl[wc] = make_uint2(l01, l23);
        }
      }
      __syncthreads();

      // S = Q @ K^T (64x32)
      {
        float sf[2][4] = {};
        int r1 = 16 * smt + g, r2 = r1 + 8;
#pragma unroll
        for (int c4 = 0; c4 < 4; c4++) {
          int kw = 8 * c4;
          uint32_t ah[4], al[4];
          ah[0] = Qh[r1 * WB + kw + tg];
          ah[1] = Qh[r2 * WB + kw + tg];
          ah[2] = Qh[r1 * WB + kw + 4 + tg];
          ah[3] = Qh[r2 * WB + kw + 4 + tg];
          al[0] = Ql[r1 * WB + kw + tg];
          al[1] = Ql[r2 * WB + kw + tg];
          al[2] = Ql[r1 * WB + kw + 4 + tg];
          al[3] = Ql[r2 * WB + kw + 4 + tg];
#pragma unroll
          for (int u2 = 0; u2 < 2; u2++) {
            int br = 16 * snh + 8 * u2 + g;
            uint32_t bh0 = Kh[br * WB + kw + tg];
            uint32_t bh1 = Kh[br * WB + kw + 4 + tg];
            uint32_t bl0 = Kl[br * WB + kw + tg];
            uint32_t bl1 = Kl[br * WB + kw + 4 + tg];
            mmax2(sf[u2], ah, al, bh0, bh1, bl0, bl1);
          }
        }
#pragma unroll
        for (int u2 = 0; u2 < 2; u2++) {
          int n0 = 16 * snh + 8 * u2 + 2 * tg;
          *(float2*)&Ss[r1 * PS + n0] = make_float2(sf[u2][0], sf[u2][1]);
          *(float2*)&Ss[r2 * PS + n0] = make_float2(sf[u2][2], sf[u2][3]);
        }
      }
      // G[j][slot] = Qr[j] . Ers[slot] (32x96)
      {
        float gf[3][4] = {};
        int r1 = 16 * gmt + g, r2 = r1 + 8;
#pragma unroll
        for (int c4 = 0; c4 < 4; c4++) {
          int kw = 8 * c4;
          uint32_t ah[4], al[4];
          ah[0] = Qrh[r1 * WB + kw + tg];
          ah[1] = Qrh[r2 * WB + kw + tg];
          ah[2] = Qrh[r1 * WB + kw + 4 + tg];
          ah[3] = Qrh[r2 * WB + kw + 4 + tg];
          al[0] = Qrl[r1 * WB + kw + tg];
          al[1] = Qrl[r2 * WB + kw + tg];
          al[2] = Qrl[r1 * WB + kw + 4 + tg];
          al[3] = Qrl[r2 * WB + kw + 4 + tg];
#pragma unroll
          for (int v = 0; v < 3; v++) {
            int br = 8 * (3 * gnb + v) + g;
            uint32_t bh0 = Erh[br * WB + kw + tg];
            uint32_t bh1 = Erh[br * WB + kw + 4 + tg];
            uint32_t bl0 = Erl[br * WB + kw + tg];
            uint32_t bl1 = Erl[br * WB + kw + 4 + tg];
            mmax2(gf[v], ah, al, bh0, bh1, bl0, bl1);
          }
        }
#pragma unroll
        for (int v = 0; v < 3; v++) {
          int n0 = 8 * (3 * gnb + v) + 2 * tg;
          *(float2*)&Gs[r1 * PG + n0] = make_float2(gf[v][0], gf[v][1]);
          *(float2*)&Gs[r2 * PG + n0] = make_float2(gf[v][2], gf[v][3]);
        }
      }
      __syncthreads();

      // softmax
      float vvals[8];
      {
        int t = t0 + sr;
        float4 sa = *(const float4*)&Ss[sr * PS + sc];
        float4 sb = *(const float4*)&Ss[sr * PS + sc + 4];
        float sl[8] = {sa.x, sa.y, sa.z, sa.w, sb.x, sb.y, sb.z, sb.w};
        int base = rbase + sr + 31 + 2112;
        float pm = -1e30f;
#pragma unroll
        for (int c = 0; c < 8; c++) {
          int j = sc + c, s = s0 + j;
          float vv = SCALE * sl[c];
          if (s <= t - 2)
            vv += Gs[j * PG + (base - j) % 96];
          else if (s == t)
            vv += ds[sr];
          if (s > t) vv = -1e30f;
          vvals[c] = vv;
          pm = fmaxf(pm, vv);
        }
        pmax[(tid >> 6) * 64 + sr] = pm;
      }
      __syncthreads();
      if (tid < 64) {
        float mo = ms[tid];
        float mn = fmaxf(fmaxf(fmaxf(pmax[tid], pmax[64 + tid]),
                               fmaxf(pmax[128 + tid], pmax[192 + tid])),
                         mo);
        ms[tid] = mn;
        as_[tid] = __expf(mo - mn);
      }
      __syncthreads();
      {
        float mn = ms[sr];
        float p[8];
        float rs = 0.f;
#pragma unroll
        for (int c = 0; c < 8; c++) {
          p[c] = __expf(vvals[c] - mn);
          rs += p[c];
        }
        uint32_t h01, l01, h23, l23, h45, l45, h67, l67;
        pk(p[0], p[1], h01, l01);
        pk(p[2], p[3], h23, l23);
        pk(p[4], p[5], h45, l45);
        pk(p[6], p[7], h67, l67);
        int wc = sr * WP + (sc >> 1);
        *(uint2*)&Ph[wc] = make_uint2(h01, h23);
        *(uint2*)&Ph[wc + 2] = make_uint2(h45, h67);
        *(uint2*)&Pl[wc] = make_uint2(l01, l23);
        *(uint2*)&Pl[wc + 2] = make_uint2(l45, l67);
        psum[(tid >> 6) * 64 + sr] = rs;
        float aa1 = as_[16 * smt + g], aa2 = as_[16 * smt + g + 8];
#pragma unroll
        for (int v = 0; v < 4; v++) {
          O[v][0] *= aa1;
          O[v][1] *= aa1;
          O[v][2] *= aa2;
          O[v][3] *= aa2;
        }
      }
      __syncthreads();
      if (tid < 64)
        ls[tid] = as_[tid] * ls[tid] + (psum[tid] + psum[64 + tid]) +
                  (psum[128 + tid] + psum[192 + tid]);
      // O += P(64x32) @ V(32x64) via Vt
      {
        int r1 = 16 * smt + g, r2 = r1 + 8;
#pragma unroll
        for (int c2 = 0; c2 < 2; c2++) {
          int kw = 8 * c2;
          uint32_t ah[4], al[4];
          ah[0] = Ph[r1 * WP + kw + tg];
          ah[1] = Ph[r2 * WP + kw + tg];
          ah[2] = Ph[r1 * WP + kw + 4 + tg];
          ah[3] = Ph[r2 * WP + kw + 4 + tg];
          al[0] = Pl[r1 * WP + kw + tg];
          al[1] = Pl[r2 * WP + kw + tg];
          al[2] = Pl[r1 * WP + kw + 4 + tg];
          al[3] = Pl[r2 * WP + kw + 4 + tg];
#pragma unroll
          for (int v = 0; v < 4; v++) {
            int n = 32 * snh + 8 * v + g;
            uint32_t bh0 = Vth[n * WP + kw + tg];
            uint32_t bh1 = Vth[n * WP + kw + 4 + tg];
            uint32_t bl0 = Vtl[n * WP + kw + tg];
            uint32_t bl1 = Vtl[n * WP + kw + 4 + tg];
            mmax2(O[v], ah, al, bh0, bh1, bl0, bl1);
          }
        }
      }
    }

    __syncthreads();
    int r1 = 16 * smt + g, r2 = r1 + 8;
    float inv1 = 1.f / ls[r1], inv2 = 1.f / ls[r2];
#pragma unroll
    for (int v = 0; v < 4; v++) {
      int nc = 32 * snh + 8 * v + 2 * tg;
      *(float2*)&out[((size_t)b * TT + t0 + r1) * HH + nc] =
          make_float2(O[v][0] * inv1, O[v][1] * inv1);
      *(float2*)&out[((size_t)b * TT + t0 + r2) * HH + nc] =
          make_float2(O[v][2] * inv2, O[v][3] * inv2);
    }
  }
}

extern "C" void kernel_launch(void* const* d_in, const int* in_sizes, int n_in,
                              void* d_out, int out_size) {
  (void)in_sizes;
  (void)n_in;
  (void)out_size;
  const float* x = (const float*)d_in[0];
  const float* Wq = (const float*)d_in[1];
  const float* Wk = (const float*)d_in[2];
  const float* Wv = (const float*)d_in[3];
  const float* Er = (const float*)d_in[4];
  float* out = (float*)d_out;

  cudaFuncSetAttribute(qkv_mma, cudaFuncAttributeMaxDynamicSharedMemorySize,
                       QKV_WORDS * 4);
  cudaFuncSetAttribute(attn_mma, cudaFuncAttributeMaxDynamicSharedMemorySize,
                       ATTN_WORDS * 4);

  qkv_mma<<<dim3((BB * TT) / 64), 256, QKV_WORDS * 4>>>(x, Wq, Wk, Wv);
  attn_mma<<<dim3(TT / 128, BB), 256, ATTN_WORDS * 4>>>(Er, out);
}

// round 7
// speedup vs baseline: 1.6822x; 1.6822x over previous
#include <cuda_runtime.h>
#include <cuda_bf16.h>
#include <cstdint>

#define BB 16
#define TT 2048
#define CC 512
#define HH 64
#define SCALE 0.125f

__device__ float g_q[BB * TT * HH];
__device__ float g_k[BB * TT * HH];
__device__ float g_v[BB * TT * HH];
// W transposed+split: [n (0..191)][k (0..511)] bf16
__device__ __nv_bfloat16 g_wth[192 * 512];
__device__ __nv_bfloat16 g_wtl[192 * 512];

// split x,y into packed bf16 hi pair and bf16 lo (residual) pair
__device__ __forceinline__ void pk(float x, float y, uint32_t& h, uint32_t& l) {
  __nv_bfloat16 hx = __float2bfloat16(x), hy = __float2bfloat16(y);
  float rx = x - __bfloat162float(hx), ry = y - __bfloat162float(hy);
  __nv_bfloat16 lx = __float2bfloat16(rx), ly = __float2bfloat16(ry);
  h = (uint32_t)__bfloat16_as_ushort(hx) |
      ((uint32_t)__bfloat16_as_ushort(hy) << 16);
  l = (uint32_t)__bfloat16_as_ushort(lx) |
      ((uint32_t)__bfloat16_as_ushort(ly) << 16);
}
__device__ __forceinline__ void pk1(float x, __nv_bfloat16& h,
                                    __nv_bfloat16& l) {
  h = __float2bfloat16(x);
  l = __float2bfloat16(x - __bfloat162float(h));
}

// m16n8k16 bf16 MMA, A row-major, B col-major, fp32 accum
__device__ __forceinline__ void mma16(float* c, uint32_t a0, uint32_t a1,
                                      uint32_t a2, uint32_t a3, uint32_t b0,
                                      uint32_t b1) {
  asm volatile(
      "mma.sync.aligned.m16n8k16.row.col.f32.bf16.bf16.f32 "
      "{%0,%1,%2,%3}, {%4,%5,%6,%7}, {%8,%9}, {%0,%1,%2,%3};"
      : "+f"(c[0]), "+f"(c[1]), "+f"(c[2]), "+f"(c[3])
      : "r"(a0), "r"(a1), "r"(a2), "r"(a3), "r"(b0), "r"(b1));
}
// bf16x2: hi*lo + lo*hi + hi*hi
__device__ __forceinline__ void mmax2(float* c, const uint32_t* ah,
                                      const uint32_t* al, uint32_t bh0,
                                      uint32_t bh1, uint32_t bl0,
                                      uint32_t bl1) {
  mma16(c, ah[0], ah[1], ah[2], ah[3], bl0, bl1);
  mma16(c, al[0], al[1], al[2], al[3], bh0, bh1);
  mma16(c, ah[0], ah[1], ah[2], ah[3], bh0, bh1);
}

// ---------------------------------------------------------------------------
// One-shot W prep: split + transpose into g_wth/g_wtl [n][k].
// ---------------------------------------------------------------------------
__global__ __launch_bounds__(256) void prep_w(const float* __restrict__ Wq,
                                              const float* __restrict__ Wk,
                                              const float* __restrict__ Wv) {
  int idx = blockIdx.x * 256 + threadIdx.x;  // 192*512 total
  int n = idx >> 9, k = idx & 511;
  const float* Wm = n < 64 ? Wq : (n < 128 ? Wk : Wv);
  float v = Wm[(size_t)k * HH + (n & 63)];
  __nv_bfloat16 h, l;
  pk1(v, h, l);
  g_wth[idx] = h;
  g_wtl[idx] = l;
}

// ---------------------------------------------------------------------------
// QKV projection, bf16x2 m16n8k16. WT tiles streamed pre-split from gmem.
// 64 rows x 192 cols per CTA, k-chunks of 64.
// ---------------------------------------------------------------------------
#define WX 36   // words/row for X tiles (32 data + 4 pad)
#define WW 36   // words/row for WT tiles
#define QKV_WORDS (2 * 64 * WX + 2 * 192 * WW)
__global__ __launch_bounds__(256) void qkv_mma(const float* __restrict__ x) {
  extern __shared__ uint32_t qsm[];
  uint32_t* Xh = qsm;
  uint32_t* Xl = Xh + 64 * WX;
  uint32_t* WTh = Xl + 64 * WX;
  uint32_t* WTl = WTh + 192 * WW;
  int tid = threadIdx.x, w = tid >> 5, lane = tid & 31;
  int g = lane >> 2, tg = lane & 3;
  int row0 = blockIdx.x * 64;
  int mt = w & 3, nh = w >> 2;
  float acc[12][4] = {};

  for (int k0 = 0; k0 < CC; k0 += 64) {
    __syncthreads();
    for (int i = tid; i < 1024; i += 256) {  // X 64x64 floats, split
      int r = i >> 4, h4 = (i & 15) << 2;
      float4 v4 = *(const float4*)&x[(size_t)(row0 + r) * CC + k0 + h4];
      uint32_t h01, l01, h23, l23;
      pk(v4.x, v4.y, h01, l01);
      pk(v4.z, v4.w, h23, l23);
      int wc = r * WX + (h4 >> 1);
      *(uint2*)&Xh[wc] = make_uint2(h01, h23);
      *(uint2*)&Xl[wc] = make_uint2(l01, l23);
    }
    for (int i = tid; i < 1536; i += 256) {  // WT 192 rows x 32 words, uint4
      int n = i >> 3, w4 = (i & 7) << 2;
      int src = n * 256 + (k0 >> 1) + w4;  // word index into g_wth
      *(uint4*)&WTh[n * WW + w4] = *(const uint4*)((const uint32_t*)g_wth + src);
      *(uint4*)&WTl[n * WW + w4] = *(const uint4*)((const uint32_t*)g_wtl + src);
    }
    __syncthreads();
    int r1 = 16 * mt + g, r2 = r1 + 8;
#pragma unroll
    for (int c4 = 0; c4 < 4; c4++) {
      int kw = 8 * c4;
      uint32_t ah[4], al[4];
      ah[0] = Xh[r1 * WX + kw + tg];
      ah[1] = Xh[r2 * WX + kw + tg];
      ah[2] = Xh[r1 * WX + kw + 4 + tg];
      ah[3] = Xh[r2 * WX + kw + 4 + tg];
      al[0] = Xl[r1 * WX + kw + tg];
      al[1] = Xl[r2 * WX + kw + tg];
      al[2] = Xl[r1 * WX + kw + 4 + tg];
      al[3] = Xl[r2 * WX + kw + 4 + tg];
#pragma unroll
      for (int v = 0; v < 12; v++) {
        int n = 8 * (12 * nh + v) + g;
        uint32_t bh0 = WTh[n * WW + kw + tg];
        uint32_t bh1 = WTh[n * WW + kw + 4 + tg];
        uint32_t bl0 = WTl[n * WW + kw + tg];
        uint32_t bl1 = WTl[n * WW + kw + 4 + tg];
        mmax2(acc[v], ah, al, bh0, bh1, bl0, bl1);
      }
    }
  }
#pragma unroll
  for (int v = 0; v < 12; v++) {
    int ncol = 8 * (12 * nh + v) + 2 * tg;
    int m = ncol >> 6, nn = ncol & 63;
    float* o = m == 0 ? g_q : (m == 1 ? g_k : g_v);
    int r0 = row0 + 16 * mt + g;
    *(float2*)&o[(size_t)r0 * HH + nn] = make_float2(acc[v][0], acc[v][1]);
    *(float2*)&o[(size_t)(r0 + 8) * HH + nn] =
        make_float2(acc[v][2], acc[v][3]);
  }
}

// ---------------------------------------------------------------------------
// Fused attention, bf16x2 everywhere. Paired tiles (t0, T-64-t0) per CTA.
// Circular 96-slot Er band, V and P split at fill/softmax time.
// ---------------------------------------------------------------------------
#define WB 36  // words/row (72 bf16): Q,K,Qr,Er
#define WP 20  // words/row (40 bf16): P, Vt
#define PS 36
#define PG 104
#define ATTN_WORDS                                                      \
  (2 * 64 * WB + 4 * 32 * WB + 2 * 96 * WB + 2 * 64 * WP + 2 * 64 * WP + \
   64 * PS + 32 * PG + 4 * 64 + 512)

__global__ __launch_bounds__(256, 2) void attn_mma(
    const float* __restrict__ Er, float* __restrict__ out) {
  extern __shared__ uint32_t sm[];
  uint32_t* Qh = sm;
  uint32_t* Ql = Qh + 64 * WB;
  uint32_t* Kh = Ql + 64 * WB;
  uint32_t* Kl = Kh + 32 * WB;
  uint32_t* Qrh = Kl + 32 * WB;
  uint32_t* Qrl = Qrh + 32 * WB;
  uint32_t* Erh = Qrl + 32 * WB;
  uint32_t* Erl = Erh + 96 * WB;
  uint32_t* Vth = Erl + 96 * WB;  // [64 h][32 s] transposed
  uint32_t* Vtl = Vth + 64 * WP;
  uint32_t* Ph = Vtl + 64 * WP;
  uint32_t* Pl = Ph + 64 * WP;
  float* Ss = (float*)(Pl + 64 * WP);  // 64 x PS
  float* Gs = Ss + 64 * PS;            // 32 x PG
  float* ds = Gs + 32 * PG;
  float* ms = ds + 64;
  float* ls = ms + 64;
  float* as_ = ls + 64;
  float* pmax = as_ + 64;  // 4 x 64
  float* psum = pmax + 256;

  int tid = threadIdx.x, w = tid >> 5, lane = tid & 31;
  int g = lane >> 2, tg = lane & 3;
  int b = blockIdx.y;
  const float* Q = g_q + (size_t)b * TT * HH;
  const float* K = g_k + (size_t)b * TT * HH;
  const float* V = g_v + (size_t)b * TT * HH;

  int smt = w & 3, snh = w >> 2;
  int gmt = w & 1, gnb = w >> 1;
  int sr = tid & 63, sc = (tid >> 6) << 3;

  for (int half = 0; half < 2; half++) {
    int t0 = half == 0 ? blockIdx.x * 64 : (TT - 64 - blockIdx.x * 64);
    __syncthreads();
    for (int i = tid; i < 1024; i += 256) {  // Q tile 64x64
      int r = i >> 4, h4 = (i & 15) << 2;
      float4 v4 = *(const float4*)&Q[(size_t)(t0 + r) * HH + h4];
      uint32_t h01, l01, h23, l23;
      pk(v4.x, v4.y, h01, l01);
      pk(v4.z, v4.w, h23, l23);
      int wc = r * WB + (h4 >> 1);
      *(uint2*)&Qh[wc] = make_uint2(h01, h23);
      *(uint2*)&Ql[wc] = make_uint2(l01, l23);
    }
    __syncthreads();
    if (tid < 64) {
      const __nv_bfloat16* qh = (const __nv_bfloat16*)Qh + tid * 2 * WB;
      const __nv_bfloat16* ql = (const __nv_bfloat16*)Ql + tid * 2 * WB;
      const float* el = Er + (size_t)(TT - 1) * HH;
      float acc = 0.f;
#pragma unroll
      for (int h = 0; h < HH; h++)
        acc += (__bfloat162float(qh[h]) + __bfloat162float(ql[h])) * el[h];
      ds[tid] = acc;
      ms[tid] = -1e30f;
      ls[tid] = 0.f;
    }

    float O[4][4] = {};
    int niter = t0 / 32 + 2;

    for (int it = 0; it < niter; it++) {
      int s0 = it * 32;
      int rbase = t0 - s0 - 33;
      __syncthreads();
      for (int i = tid; i < 512; i += 256) {  // K, Vt, Qr tiles
        int r = i >> 4, h4 = (i & 15) << 2;
        int wc = r * WB + (h4 >> 1);
        uint32_t h01, l01, h23, l23;
        float4 kv = *(const float4*)&K[(size_t)(s0 + r) * HH + h4];
        pk(kv.x, kv.y, h01, l01);
        pk(kv.z, kv.w, h23, l23);
        *(uint2*)&Kh[wc] = make_uint2(h01, h23);
        *(uint2*)&Kl[wc] = make_uint2(l01, l23);
        float4 vv = *(const float4*)&V[(size_t)(s0 + r) * HH + h4];
        {  // transposed V: Vt[h][s]
          __nv_bfloat16* vth = (__nv_bfloat16*)Vth;
          __nv_bfloat16* vtl = (__nv_bfloat16*)Vtl;
          __nv_bfloat16 hb, lb;
          pk1(vv.x, hb, lb);
          vth[(h4 + 0) * 2 * WP + r] = hb;
          vtl[(h4 + 0) * 2 * WP + r] = lb;
          pk1(vv.y, hb, lb);
          vth[(h4 + 1) * 2 * WP + r] = hb;
          vtl[(h4 + 1) * 2 * WP + r] = lb;
          pk1(vv.z, hb, lb);
          vth[(h4 + 2) * 2 * WP + r] = hb;
          vtl[(h4 + 2) * 2 * WP + r] = lb;
          pk1(vv.w, hb, lb);
          vth[(h4 + 3) * 2 * WP + r] = hb;
          vtl[(h4 + 3) * 2 * WP + r] = lb;
        }
        int rq = s0 + 1 + r;
        if (rq > TT - 1) rq = TT - 1;  // clamped rows feed only masked slots
        float4 qv = *(const float4*)&Q[(size_t)rq * HH + h4];
        pk(qv.x, qv.y, h01, l01);
        pk(qv.z, qv.w, h23, l23);
        *(uint2*)&Qrh[wc] = make_uint2(h01, h23);
        *(uint2*)&Qrl[wc] = make_uint2(l01, l23);
      }
      {  // Er band: 96 slots first iter, 32 new rows after
        int nel = (it == 0 ? 96 : 32) * 16;
        for (int i = tid; i < nel; i += 256) {
          int xr = i >> 4, h4 = (i & 15) << 2;
          int r = rbase + xr;
          int slot = (r + 2112) % 96;
          int rc = r < 0 ? 0 : r;  // negative rows unused (masked)
          float4 ev = *(const float4*)&Er[(size_t)rc * HH + h4];
          uint32_t h01, l01, h23, l23;
          pk(ev.x, ev.y, h01, l01);
          pk(ev.z, ev.w, h23, l23);
          int wc = slot * WB + (h4 >> 1);
          *(uint2*)&Erh[wc] = make_uint2(h01, h23);
          *(uint2*)&Erl[wc] = make_uint2(l01, l23);
        }
      }
      __syncthreads();

      // S = Q @ K^T (64x32)
      {
        float sf[2][4] = {};
        int r1 = 16 * smt + g, r2 = r1 + 8;
#pragma unroll
        for (int c4 = 0; c4 < 4; c4++) {
          int kw = 8 * c4;
          uint32_t ah[4], al[4];
          ah[0] = Qh[r1 * WB + kw + tg];
          ah[1] = Qh[r2 * WB + kw + tg];
          ah[2] = Qh[r1 * WB + kw + 4 + tg];
          ah[3] = Qh[r2 * WB + kw + 4 + tg];
          al[0] = Ql[r1 * WB + kw + tg];
          al[1] = Ql[r2 * WB + kw + tg];
          al[2] = Ql[r1 * WB + kw + 4 + tg];
          al[3] = Ql[r2 * WB + kw + 4 + tg];
#pragma unroll
          for (int u2 = 0; u2 < 2; u2++) {
            int br = 16 * snh + 8 * u2 + g;
            uint32_t bh0 = Kh[br * WB + kw + tg];
            uint32_t bh1 = Kh[br * WB + kw + 4 + tg];
            uint32_t bl0 = Kl[br * WB + kw + tg];
            uint32_t bl1 = Kl[br * WB + kw + 4 + tg];
            mmax2(sf[u2], ah, al, bh0, bh1, bl0, bl1);
          }
        }
#pragma unroll
        for (int u2 = 0; u2 < 2; u2++) {
          int n0 = 16 * snh + 8 * u2 + 2 * tg;
          *(float2*)&Ss[r1 * PS + n0] = make_float2(sf[u2][0], sf[u2][1]);
          *(float2*)&Ss[r2 * PS + n0] = make_float2(sf[u2][2], sf[u2][3]);
        }
      }
      // G[j][slot] = Qr[j] . Ers[slot] (32x96)
      {
        float gf[3][4] = {};
        int r1 = 16 * gmt + g, r2 = r1 + 8;
#pragma unroll
        for (int c4 = 0; c4 < 4; c4++) {
          int kw = 8 * c4;
          uint32_t ah[4], al[4];
          ah[0] = Qrh[r1 * WB + kw + tg];
          ah[1] = Qrh[r2 * WB + kw + tg];
          ah[2] = Qrh[r1 * WB + kw + 4 + tg];
          ah[3] = Qrh[r2 * WB + kw + 4 + tg];
          al[0] = Qrl[r1 * WB + kw + tg];
          al[1] = Qrl[r2 * WB + kw + tg];
          al[2] = Qrl[r1 * WB + kw + 4 + tg];
          al[3] = Qrl[r2 * WB + kw + 4 + tg];
#pragma unroll
          for (int v = 0; v < 3; v++) {
            int br = 8 * (3 * gnb + v) + g;
            uint32_t bh0 = Erh[br * WB + kw + tg];
            uint32_t bh1 = Erh[br * WB + kw + 4 + tg];
            uint32_t bl0 = Erl[br * WB + kw + tg];
            uint32_t bl1 = Erl[br * WB + kw + 4 + tg];
            mmax2(gf[v], ah, al, bh0, bh1, bl0, bl1);
          }
        }
#pragma unroll
        for (int v = 0; v < 3; v++) {
          int n0 = 8 * (3 * gnb + v) + 2 * tg;
          *(float2*)&Gs[r1 * PG + n0] = make_float2(gf[v][0], gf[v][1]);
          *(float2*)&Gs[r2 * PG + n0] = make_float2(gf[v][2], gf[v][3]);
        }
      }
      __syncthreads();

      // softmax
      float vvals[8];
      {
        int t = t0 + sr;
        float4 sa = *(const float4*)&Ss[sr * PS + sc];
        float4 sb = *(const float4*)&Ss[sr * PS + sc + 4];
        float sl[8] = {sa.x, sa.y, sa.z, sa.w, sb.x, sb.y, sb.z, sb.w};
        int base = rbase + sr + 31 + 2112;
        float pm = -1e30f;
#pragma unroll
        for (int c = 0; c < 8; c++) {
          int j = sc + c, s = s0 + j;
          float vv = SCALE * sl[c];
          if (s <= t - 2)
            vv += Gs[j * PG + (base - j) % 96];
          else if (s == t)
            vv += ds[sr];
          if (s > t) vv = -1e30f;
          vvals[c] = vv;
          pm = fmaxf(pm, vv);
        }
        pmax[(tid >> 6) * 64 + sr] = pm;
      }
      __syncthreads();
      if (tid < 64) {
        float mo = ms[tid];
        float mn = fmaxf(fmaxf(fmaxf(pmax[tid], pmax[64 + tid]),
                               fmaxf(pmax[128 + tid], pmax[192 + tid])),
                         mo);
        ms[tid] = mn;
        as_[tid] = __expf(mo - mn);
      }
      __syncthreads();
      {
        float mn = ms[sr];
        float p[8];
        float rs = 0.f;
#pragma unroll
        for (int c = 0; c < 8; c++) {
          p[c] = __expf(vvals[c] - mn);
          rs += p[c];
        }
        uint32_t h01, l01, h23, l23, h45, l45, h67, l67;
        pk(p[0], p[1], h01, l01);
        pk(p[2], p[3], h23, l23);
        pk(p[4], p[5], h45, l45);
        pk(p[6], p[7], h67, l67);
        int wc = sr * WP + (sc >> 1);
        *(uint2*)&Ph[wc] = make_uint2(h01, h23);
        *(uint2*)&Ph[wc + 2] = make_uint2(h45, h67);
        *(uint2*)&Pl[wc] = make_uint2(l01, l23);
        *(uint2*)&Pl[wc + 2] = make_uint2(l45, l67);
        psum[(tid >> 6) * 64 + sr] = rs;
        float aa1 = as_[16 * smt + g], aa2 = as_[16 * smt + g + 8];
#pragma unroll
        for (int v = 0; v < 4; v++) {
          O[v][0] *= aa1;
          O[v][1] *= aa1;
          O[v][2] *= aa2;
          O[v][3] *= aa2;
        }
      }
      __syncthreads();
      if (tid < 64)
        ls[tid] = as_[tid] * ls[tid] + (psum[tid] + psum[64 + tid]) +
                  (psum[128 + tid] + psum[192 + tid]);
      // O += P(64x32) @ V(32x64) via Vt
      {
        int r1 = 16 * smt + g, r2 = r1 + 8;
#pragma unroll
        for (int c2 = 0; c2 < 2; c2++) {
          int kw = 8 * c2;
          uint32_t ah[4], al[4];
          ah[0] = Ph[r1 * WP + kw + tg];
          ah[1] = Ph[r2 * WP + kw + tg];
          ah[2] = Ph[r1 * WP + kw + 4 + tg];
          ah[3] = Ph[r2 * WP + kw + 4 + tg];
          al[0] = Pl[r1 * WP + kw + tg];
          al[1] = Pl[r2 * WP + kw + tg];
          al[2] = Pl[r1 * WP + kw + 4 + tg];
          al[3] = Pl[r2 * WP + kw + 4 + tg];
#pragma unroll
          for (int v = 0; v < 4; v++) {
            int n = 32 * snh + 8 * v + g;
            uint32_t bh0 = Vth[n * WP + kw + tg];
            uint32_t bh1 = Vth[n * WP + kw + 4 + tg];
            uint32_t bl0 = Vtl[n * WP + kw + tg];
            uint32_t bl1 = Vtl[n * WP + kw + 4 + tg];
            mmax2(O[v], ah, al, bh0, bh1, bl0, bl1);
          }
        }
      }
    }

    __syncthreads();
    int r1 = 16 * smt + g, r2 = r1 + 8;
    float inv1 = 1.f / ls[r1], inv2 = 1.f / ls[r2];
#pragma unroll
    for (int v = 0; v < 4; v++) {
      int nc = 32 * snh + 8 * v + 2 * tg;
      *(float2*)&out[((size_t)b * TT + t0 + r1) * HH + nc] =
          make_float2(O[v][0] * inv1, O[v][1] * inv1);
      *(float2*)&out[((size_t)b * TT + t0 + r2) * HH + nc] =
          make_float2(O[v][2] * inv2, O[v][3] * inv2);
    }
  }
}

extern "C" void kernel_launch(void* const* d_in, const int* in_sizes, int n_in,
                              void* d_out, int out_size) {
  (void)in_sizes;
  (void)n_in;
  (void)out_size;
  const float* x = (const float*)d_in[0];
  const float* Wq = (const float*)d_in[1];
  const float* Wk = (const float*)d_in[2];
  const float* Wv = (const float*)d_in[3];
  const float* Er = (const float*)d_in[4];
  float* out = (float*)d_out;

  cudaFuncSetAttribute(qkv_mma, cudaFuncAttributeMaxDynamicSharedMemorySize,
                       QKV_WORDS * 4);
  cudaFuncSetAttribute(attn_mma, cudaFuncAttributeMaxDynamicSharedMemorySize,
                       ATTN_WORDS * 4);

  prep_w<<<dim3(192 * 512 / 256), 256>>>(Wq, Wk, Wv);
  qkv_mma<<<dim3((BB * TT) / 64), 256, QKV_WORDS * 4>>>(x);
  attn_mma<<<dim3(TT / 128, BB), 256, ATTN_WORDS * 4>>>(Er, out);
}

// round 9
// speedup vs baseline: 1.7345x; 1.0311x over previous
#include <cuda_runtime.h>
#include <cuda_bf16.h>
#include <cstdint>

#define BB 16
#define TT 2048
#define CC 512
#define HH 64
#define SCALE 0.125f

__device__ float g_q[BB * TT * HH];
__device__ float g_k[BB * TT * HH];
__device__ float g_v[BB * TT * HH];
// W transposed+split: [n (0..191)][k (0..511)] bf16
__device__ __nv_bfloat16 g_wth[192 * 512];
__device__ __nv_bfloat16 g_wtl[192 * 512];

// split x,y into packed bf16 hi pair and bf16 lo (residual) pair
__device__ __forceinline__ void pk(float x, float y, uint32_t& h, uint32_t& l) {
  __nv_bfloat16 hx = __float2bfloat16(x), hy = __float2bfloat16(y);
  float rx = x - __bfloat162float(hx), ry = y - __bfloat162float(hy);
  __nv_bfloat16 lx = __float2bfloat16(rx), ly = __float2bfloat16(ry);
  h = (uint32_t)__bfloat16_as_ushort(hx) |
      ((uint32_t)__bfloat16_as_ushort(hy) << 16);
  l = (uint32_t)__bfloat16_as_ushort(lx) |
      ((uint32_t)__bfloat16_as_ushort(ly) << 16);
}
__device__ __forceinline__ void pk1(float x, __nv_bfloat16& h,
                                    __nv_bfloat16& l) {
  h = __float2bfloat16(x);
  l = __float2bfloat16(x - __bfloat162float(h));
}

// m16n8k16 bf16 MMA, A row-major, B col-major, fp32 accum
__device__ __forceinline__ void mma16(float* c, uint32_t a0, uint32_t a1,
                                      uint32_t a2, uint32_t a3, uint32_t b0,
                                      uint32_t b1) {
  asm volatile(
      "mma.sync.aligned.m16n8k16.row.col.f32.bf16.bf16.f32 "
      "{%0,%1,%2,%3}, {%4,%5,%6,%7}, {%8,%9}, {%0,%1,%2,%3};"
      : "+f"(c[0]), "+f"(c[1]), "+f"(c[2]), "+f"(c[3])
      : "r"(a0), "r"(a1), "r"(a2), "r"(a3), "r"(b0), "r"(b1));
}
// bf16x2: hi*lo + lo*hi + hi*hi
__device__ __forceinline__ void mmax2(float* c, const uint32_t* ah,
                                      const uint32_t* al, uint32_t bh0,
                                      uint32_t bh1, uint32_t bl0,
                                      uint32_t bl1) {
  mma16(c, ah[0], ah[1], ah[2], ah[3], bl0, bl1);
  mma16(c, al[0], al[1], al[2], al[3], bh0, bh1);
  mma16(c, ah[0], ah[1], ah[2], ah[3], bh0, bh1);
}

// ---------------------------------------------------------------------------
// One-shot W prep: split + transpose into g_wth/g_wtl [n][k].
// ---------------------------------------------------------------------------
__global__ __launch_bounds__(256) void prep_w(const float* __restrict__ Wq,
                                              const float* __restrict__ Wk,
                                              const float* __restrict__ Wv) {
  int idx = blockIdx.x * 256 + threadIdx.x;  // 192*512 total
  int n = idx >> 9, k = idx & 511;
  const float* Wm = n < 64 ? Wq : (n < 128 ? Wk : Wv);
  float v = Wm[(size_t)k * HH + (n & 63)];
  __nv_bfloat16 h, l;
  pk1(v, h, l);
  g_wth[idx] = h;
  g_wtl[idx] = l;
}

// ---------------------------------------------------------------------------
// QKV projection, bf16x2 m16n8k16. WT tiles streamed pre-split from gmem.
// ---------------------------------------------------------------------------
#define WX 36
#define WW 36
#define QKV_WORDS (2 * 64 * WX + 2 * 192 * WW)
__global__ __launch_bounds__(256) void qkv_mma(const float* __restrict__ x) {
  extern __shared__ uint32_t qsm[];
  uint32_t* Xh = qsm;
  uint32_t* Xl = Xh + 64 * WX;
  uint32_t* WTh = Xl + 64 * WX;
  uint32_t* WTl = WTh + 192 * WW;
  int tid = threadIdx.x, w = tid >> 5, lane = tid & 31;
  int g = lane >> 2, tg = lane & 3;
  int row0 = blockIdx.x * 64;
  int mt = w & 3, nh = w >> 2;
  float acc[12][4] = {};

  for (int k0 = 0; k0 < CC; k0 += 64) {
    __syncthreads();
    for (int i = tid; i < 1024; i += 256) {  // X 64x64 floats, split
      int r = i >> 4, h4 = (i & 15) << 2;
      float4 v4 = *(const float4*)&x[(size_t)(row0 + r) * CC + k0 + h4];
      uint32_t h01, l01, h23, l23;
      pk(v4.x, v4.y, h01, l01);
      pk(v4.z, v4.w, h23, l23);
      int wc = r * WX + (h4 >> 1);
      *(uint2*)&Xh[wc] = make_uint2(h01, h23);
      *(uint2*)&Xl[wc] = make_uint2(l01, l23);
    }
    for (int i = tid; i < 1536; i += 256) {  // WT 192 rows x 32 words, uint4
      int n = i >> 3, w4 = (i & 7) << 2;
      int src = n * 256 + (k0 >> 1) + w4;
      *(uint4*)&WTh[n * WW + w4] = *(const uint4*)((const uint32_t*)g_wth + src);
      *(uint4*)&WTl[n * WW + w4] = *(const uint4*)((const uint32_t*)g_wtl + src);
    }
    __syncthreads();
    int r1 = 16 * mt + g, r2 = r1 + 8;
#pragma unroll
    for (int c4 = 0; c4 < 4; c4++) {
      int kw = 8 * c4;
      uint32_t ah[4], al[4];
      ah[0] = Xh[r1 * WX + kw + tg];
      ah[1] = Xh[r2 * WX + kw + tg];
      ah[2] = Xh[r1 * WX + kw + 4 + tg];
      ah[3] = Xh[r2 * WX + kw + 4 + tg];
      al[0] = Xl[r1 * WX + kw + tg];
      al[1] = Xl[r2 * WX + kw + tg];
      al[2] = Xl[r1 * WX + kw + 4 + tg];
      al[3] = Xl[r2 * WX + kw + 4 + tg];
#pragma unroll
      for (int v = 0; v < 12; v++) {
        int n = 8 * (12 * nh + v) + g;
        uint32_t bh0 = WTh[n * WW + kw + tg];
        uint32_t bh1 = WTh[n * WW + kw + 4 + tg];
        uint32_t bl0 = WTl[n * WW + kw + tg];
        uint32_t bl1 = WTl[n * WW + kw + 4 + tg];
        mmax2(acc[v], ah, al, bh0, bh1, bl0, bl1);
      }
    }
  }
#pragma unroll
  for (int v = 0; v < 12; v++) {
    int ncol = 8 * (12 * nh + v) + 2 * tg;
    int m = ncol >> 6, nn = ncol & 63;
    float* o = m == 0 ? g_q : (m == 1 ? g_k : g_v);
    int r0 = row0 + 16 * mt + g;
    *(float2*)&o[(size_t)r0 * HH + nn] = make_float2(acc[v][0], acc[v][1]);
    *(float2*)&o[(size_t)(r0 + 8) * HH + nn] =
        make_float2(acc[v][2], acc[v][3]);
  }
}

// ---------------------------------------------------------------------------
// Fused attention, bf16x2, warp-specialized:
//   warps 0-3: S = Q@K^T (16 full rows each) + in-register softmax
//   warps 4-7: G = Qr@Ers^T (gather table for rel term)
//   all 8:     O += P@V
// 4 syncthreads per key tile (was 6); no score smem round trip.
// ---------------------------------------------------------------------------
#define WB 36  // words/row (72 bf16): Q,K,Qr,Er
#define WP 20  // words/row (40 bf16): P, Vt
#define PG 104
#define ATTN_WORDS                                                       \
  (2 * 64 * WB + 4 * 32 * WB + 2 * 96 * WB + 2 * 64 * WP + 2 * 64 * WP + \
   32 * PG + 3 * 64)

__global__ __launch_bounds__(256, 2) void attn_mma(
    const float* __restrict__ Er, float* __restrict__ out) {
  extern __shared__ uint32_t sm[];
  uint32_t* Qh = sm;
  uint32_t* Ql = Qh + 64 * WB;
  uint32_t* Kh = Ql + 64 * WB;
  uint32_t* Kl = Kh + 32 * WB;
  uint32_t* Qrh = Kl + 32 * WB;
  uint32_t* Qrl = Qrh + 32 * WB;
  uint32_t* Erh = Qrl + 32 * WB;
  uint32_t* Erl = Erh + 96 * WB;
  uint32_t* Vth = Erl + 96 * WB;  // [64 h][32 s] transposed
  uint32_t* Vtl = Vth + 64 * WP;
  uint32_t* Ph = Vtl + 64 * WP;
  uint32_t* Pl = Ph + 64 * WP;
  float* Gs = (float*)(Pl + 64 * WP);  // 32 x PG
  float* ds = Gs + 32 * PG;            // 64
  float* as_ = ds + 64;                // 64 (alpha per row)
  float* lsm = as_ + 64;               // 64 (final l per row)

  int tid = threadIdx.x, w = tid >> 5, lane = tid & 31;
  int g = lane >> 2, tg = lane & 3;
  int b = blockIdx.y;
  const float* Q = g_q + (size_t)b * TT * HH;
  const float* K = g_k + (size_t)b * TT * HH;
  const float* V = g_v + (size_t)b * TT * HH;

  int smt = w & 3, snh = w >> 2;  // AV partition

  for (int half = 0; half < 2; half++) {
    int t0 = half == 0 ? blockIdx.x * 64 : (TT - 64 - blockIdx.x * 64);
    __syncthreads();
    for (int i = tid; i < 1024; i += 256) {  // Q tile 64x64
      int r = i >> 4, h4 = (i & 15) << 2;
      float4 v4 = *(const float4*)&Q[(size_t)(t0 + r) * HH + h4];
      uint32_t h01, l01, h23, l23;
      pk(v4.x, v4.y, h01, l01);
      pk(v4.z, v4.w, h23, l23);
      int wc = r * WB + (h4 >> 1);
      *(uint2*)&Qh[wc] = make_uint2(h01, h23);
      *(uint2*)&Ql[wc] = make_uint2(l01, l23);
    }
    __syncthreads();
    if (tid < 64) {
      const __nv_bfloat16* qh = (const __nv_bfloat16*)Qh + tid * 2 * WB;
      const __nv_bfloat16* ql = (const __nv_bfloat16*)Ql + tid * 2 * WB;
      const float* el = Er + (size_t)(TT - 1) * HH;
      float acc = 0.f;
#pragma unroll
      for (int h = 0; h < HH; h++)
        acc += (__bfloat162float(qh[h]) + __bfloat162float(ql[h])) * el[h];
      ds[tid] = acc;
    }

    float O[4][4] = {};
    float m_a = -1e30f, m_b = -1e30f, l_a = 0.f, l_b = 0.f;
    int niter = t0 / 32 + 2;

    for (int it = 0; it < niter; it++) {
      int s0 = it * 32;
      int rbase = t0 - s0 - 33;
      __syncthreads();
      for (int i = tid; i < 512; i += 256) {  // K, Vt, Qr tiles
        int r = i >> 4, h4 = (i & 15) << 2;
        int wc = r * WB + (h4 >> 1);
        uint32_t h01, l01, h23, l23;
        float4 kv = *(const float4*)&K[(size_t)(s0 + r) * HH + h4];
        pk(kv.x, kv.y, h01, l01);
        pk(kv.z, kv.w, h23, l23);
        *(uint2*)&Kh[wc] = make_uint2(h01, h23);
        *(uint2*)&Kl[wc] = make_uint2(l01, l23);
        float4 vv = *(const float4*)&V[(size_t)(s0 + r) * HH + h4];
        {  // transposed V: Vt[h][s]
          __nv_bfloat16* vth = (__nv_bfloat16*)Vth;
          __nv_bfloat16* vtl = (__nv_bfloat16*)Vtl;
          __nv_bfloat16 hb, lb;
          pk1(vv.x, hb, lb);
          vth[(h4 + 0) * 2 * WP + r] = hb;
          vtl[(h4 + 0) * 2 * WP + r] = lb;
          pk1(vv.y, hb, lb);
          vth[(h4 + 1) * 2 * WP + r] = hb;
          vtl[(h4 + 1) * 2 * WP + r] = lb;
          pk1(vv.z, hb, lb);
          vth[(h4 + 2) * 2 * WP + r] = hb;
          vtl[(h4 + 2) * 2 * WP + r] = lb;
          pk1(vv.w, hb, lb);
          vth[(h4 + 3) * 2 * WP + r] = hb;
          vtl[(h4 + 3) * 2 * WP + r] = lb;
        }
        int rq = s0 + 1 + r;
        if (rq > TT - 1) rq = TT - 1;  // clamped rows feed only masked slots
        float4 qv = *(const float4*)&Q[(size_t)rq * HH + h4];
        pk(qv.x, qv.y, h01, l01);
        pk(qv.z, qv.w, h23, l23);
        *(uint2*)&Qrh[wc] = make_uint2(h01, h23);
        *(uint2*)&Qrl[wc] = make_uint2(l01, l23);
      }
      {  // Er band: 96 slots first iter, 32 new rows after
        int nel = (it == 0 ? 96 : 32) * 16;
        for (int i = tid; i < nel; i += 256) {
          int xr = i >> 4, h4 = (i & 15) << 2;
          int r = rbase + xr;
          int slot = (r + 2112) % 96;
          int rc = r < 0 ? 0 : r;  // negative rows unused (masked)
          float4 ev = *(const float4*)&Er[(size_t)rc * HH + h4];
          uint32_t h01, l01, h23, l23;
          pk(ev.x, ev.y, h01, l01);
          pk(ev.z, ev.w, h23, l23);
          int wc = slot * WB + (h4 >> 1);
          *(uint2*)&Erh[wc] = make_uint2(h01, h23);
          *(uint2*)&Erl[wc] = make_uint2(l01, l23);
        }
      }
      __syncthreads();

      float sf[4][4] = {};  // S fragments (warps 0-3)
      if (w < 4) {
        // S = Q @ K^T: warp w covers rows 16w..16w+15, all 32 cols
        int r1 = 16 * w + g, r2 = r1 + 8;
#pragma unroll
        for (int c4 = 0; c4 < 4; c4++) {
          int kw = 8 * c4;
          uint32_t ah[4], al[4];
          ah[0] = Qh[r1 * WB + kw + tg];
          ah[1] = Qh[r2 * WB + kw + tg];
          ah[2] = Qh[r1 * WB + kw + 4 + tg];
          ah[3] = Qh[r2 * WB + kw + 4 + tg];
          al[0] = Ql[r1 * WB + kw + tg];
          al[1] = Ql[r2 * WB + kw + tg];
          al[2] = Ql[r1 * WB + kw + 4 + tg];
          al[3] = Ql[r2 * WB + kw + 4 + tg];
#pragma unroll
          for (int u = 0; u < 4; u++) {
            int br = 8 * u + g;
            uint32_t bh0 = Kh[br * WB + kw + tg];
            uint32_t bh1 = Kh[br * WB + kw + 4 + tg];
            uint32_t bl0 = Kl[br * WB + kw + tg];
            uint32_t bl1 = Kl[br * WB + kw + 4 + tg];
            mmax2(sf[u], ah, al, bh0, bh1, bl0, bl1);
          }
        }
      } else {
        // G[j][slot] = Qr[j].Ers[slot]: warp covers 16 rows x 48 slots
        int gw = w - 4;
        int mt2 = gw & 1, cg = gw >> 1;
        float gf[6][4] = {};
        int r1 = 16 * mt2 + g, r2 = r1 + 8;
#pragma unroll
        for (int c4 = 0; c4 < 4; c4++) {
          int kw = 8 * c4;
          uint32_t ah[4], al[4];
          ah[0] = Qrh[r1 * WB + kw + tg];
          ah[1] = Qrh[r2 * WB + kw + tg];
          ah[2] = Qrh[r1 * WB + kw + 4 + tg];
          ah[3] = Qrh[r2 * WB + kw + 4 + tg];
          al[0] = Qrl[r1 * WB + kw + tg];
          al[1] = Qrl[r2 * WB + kw + tg];
          al[2] = Qrl[r1 * WB + kw + 4 + tg];
          al[3] = Qrl[r2 * WB + kw + 4 + tg];
#pragma unroll
          for (int v = 0; v < 6; v++) {
            int br = 48 * cg + 8 * v + g;
            uint32_t bh0 = Erh[br * WB + kw + tg];
            uint32_t bh1 = Erh[br * WB + kw + 4 + tg];
            uint32_t bl0 = Erl[br * WB + kw + tg];
            uint32_t bl1 = Erl[br * WB + kw + 4 + tg];
            mmax2(gf[v], ah, al, bh0, bh1, bl0, bl1);
          }
        }
#pragma unroll
        for (int v = 0; v < 6; v++) {
          int n0 = 48 * cg + 8 * v + 2 * tg;
          *(float2*)&Gs[r1 * PG + n0] = make_float2(gf[v][0], gf[v][1]);
          *(float2*)&Gs[r2 * PG + n0] = make_float2(gf[v][2], gf[v][3]);
        }
      }
      __syncthreads();  // Gs ready for softmax

      if (w < 4) {
        // in-register softmax for rows ra=16w+g, rb=ra+8
        int ra = 16 * w + g, rb = ra + 8;
        int ta = t0 + ra, tb = t0 + rb;
        int baseA = rbase + ra + 31 + 2112;  // slot = (baseA - j) % 96
        int baseB = rbase + rb + 31 + 2112;
        float va[8], vb[8];
        float dsa = ds[ra], dsb = ds[rb];
#pragma unroll
        for (int u = 0; u < 4; u++) {
#pragma unroll
          for (int e = 0; e < 2; e++) {
            int j = 8 * u + 2 * tg + e;
            int s = s0 + j;
            float adda = 0.f, addb = 0.f;
            if (s <= ta - 2)
              adda = Gs[j * PG + (baseA - j) % 96];
            else if (s == ta)
              adda = dsa;
            if (s <= tb - 2)
              addb = Gs[j * PG + (baseB - j) % 96];
            else if (s == tb)
              addb = dsb;
            float xa = SCALE * sf[u][e] + adda;
            float xb = SCALE * sf[u][2 + e] + addb;
            if (s > ta) xa = -1e30f;
            if (s > tb) xb = -1e30f;
            va[2 * u + e] = xa;
            vb[2 * u + e] = xb;
          }
        }
        float ma = va[0], mb = vb[0];
#pragma unroll
        for (int i = 1; i < 8; i++) {
          ma = fmaxf(ma, va[i]);
          mb = fmaxf(mb, vb[i]);
        }
        ma = fmaxf(ma, __shfl_xor_sync(0xffffffffu, ma, 1));
        ma = fmaxf(ma, __shfl_xor_sync(0xffffffffu, ma, 2));
        mb = fmaxf(mb, __shfl_xor_sync(0xffffffffu, mb, 1));
        mb = fmaxf(mb, __shfl_xor_sync(0xffffffffu, mb, 2));
        float mna = fmaxf(m_a, ma), mnb = fmaxf(m_b, mb);
        float ala = __expf(m_a - mna), alb = __expf(m_b - mnb);
        m_a = mna;
        m_b = mnb;
        float pa[8], pb[8];
        float rsa = 0.f, rsb = 0.f;
#pragma unroll
        for (int i = 0; i < 8; i++) {
          pa[i] = __expf(va[i] - mna);
          pb[i] = __expf(vb[i] - mnb);
          rsa += pa[i];
          rsb += pb[i];
        }
        rsa += __shfl_xor_sync(0xffffffffu, rsa, 1);
        rsa += __shfl_xor_sync(0xffffffffu, rsa, 2);
        rsb += __shfl_xor_sync(0xffffffffu, rsb, 1);
        rsb += __shfl_xor_sync(0xffffffffu, rsb, 2);
        l_a = ala * l_a + rsa;
        l_b = alb * l_b + rsb;
#pragma unroll
        for (int u = 0; u < 4; u++) {
          uint32_t h, l;
          pk(pa[2 * u], pa[2 * u + 1], h, l);
          Ph[ra * WP + 4 * u + tg] = h;
          Pl[ra * WP + 4 * u + tg] = l;
          pk(pb[2 * u], pb[2 * u + 1], h, l);
          Ph[rb * WP + 4 * u + tg] = h;
          Pl[rb * WP + 4 * u + tg] = l;
        }
        if (tg == 0) {
          as_[ra] = ala;
          as_[rb] = alb;
        }
      }
      __syncthreads();  // P, as_ ready

      // O += P(64x32) @ V(32x64) via Vt, all warps
      {
        int r1 = 16 * smt + g, r2 = r1 + 8;
        float aa1 = as_[r1], aa2 = as_[r2];
#pragma unroll
        for (int v = 0; v < 4; v++) {
          O[v][0] *= aa1;
          O[v][1] *= aa1;
          O[v][2] *= aa2;
          O[v][3] *= aa2;
        }
#pragma unroll
        for (int c2 = 0; c2 < 2; c2++) {
          int kw = 8 * c2;
          uint32_t ah[4], al[4];
          ah[0] = Ph[r1 * WP + kw + tg];
          ah[1] = Ph[r2 * WP + kw + tg];
          ah[2] = Ph[r1 * WP + kw + 4 + tg];
          ah[3] = Ph[r2 * WP + kw + 4 + tg];
          al[0] = Pl[r1 * WP + kw + tg];
          al[1] = Pl[r2 * WP + kw + tg];
          al[2] = Pl[r1 * WP + kw + 4 + tg];
          al[3] = Pl[r2 * WP + kw + 4 + tg];
#pragma unroll
          for (int v = 0; v < 4; v++) {
            int n = 32 * snh + 8 * v + g;
            uint32_t bh0 = Vth[n * WP + kw + tg];
            uint32_t bh1 = Vth[n * WP + kw + 4 + tg];
            uint32_t bl0 = Vtl[n * WP + kw + tg];
            uint32_t bl1 = Vtl[n * WP + kw + 4 + tg];
            mmax2(O[v], ah, al, bh0, bh1, bl0, bl1);
          }
        }
      }
    }

    // publish l, normalize, write out
    if (w < 4 && tg == 0) {
      lsm[16 * w + g] = l_a;
      lsm[16 * w + g + 8] = l_b;
    }
    __syncthreads();
    int r1 = 16 * smt + g, r2 = r1 + 8;
    float inv1 = 1.f / lsm[r1], inv2 = 1.f / lsm[r2];
#pragma unroll
    for (int v = 0; v < 4; v++) {
      int nc = 32 * snh + 8 * v + 2 * tg;
      *(float2*)&out[((size_t)b * TT + t0 + r1) * HH + nc] =
          make_float2(O[v][0] * inv1, O[v][1] * inv1);
      *(float2*)&out[((size_t)b * TT + t0 + r2) * HH + nc] =
          make_float2(O[v][2] * inv2, O[v][3] * inv2);
    }
  }
}

extern "C" void kernel_launch(void* const* d_in, const int* in_sizes, int n_in,
                              void* d_out, int out_size) {
  (void)in_sizes;
  (void)n_in;
  (void)out_size;
  const float* x = (const float*)d_in[0];
  const float* Wq = (const float*)d_in[1];
  const float* Wk = (const float*)d_in[2];
  const float* Wv = (const float*)d_in[3];
  const float* Er = (const float*)d_in[4];
  float* out = (float*)d_out;

  cudaFuncSetAttribute(qkv_mma, cudaFuncAttributeMaxDynamicSharedMemorySize,
                       QKV_WORDS * 4);
  cudaFuncSetAttribute(attn_mma, cudaFuncAttributeMaxDynamicSharedMemorySize,
                       ATTN_WORDS * 4);

  prep_w<<<dim3(192 * 512 / 256), 256>>>(Wq, Wk, Wv);
  qkv_mma<<<dim3((BB * TT) / 64), 256, QKV_WORDS * 4>>>(x);
  attn_mma<<<dim3(TT / 128, BB), 256, ATTN_WORDS * 4>>>(Er, out);
}

// round 10
// speedup vs baseline: 1.8486x; 1.0658x over previous
#include <cuda_runtime.h>
#include <cuda_bf16.h>
#include <cstdint>

#define BB 16
#define TT 2048
#define CC 512
#define HH 64
#define SCALE 0.125f

// Q,K split bf16 (packed pairs), row-major [b*T + t][64]
__device__ __nv_bfloat16 g_qh[BB * TT * HH];
__device__ __nv_bfloat16 g_ql[BB * TT * HH];
__device__ __nv_bfloat16 g_kh[BB * TT * HH];
__device__ __nv_bfloat16 g_kl[BB * TT * HH];
// V split + transposed: [b*64 + h][t]
__device__ __nv_bfloat16 g_vth[BB * HH * TT];
__device__ __nv_bfloat16 g_vtl[BB * HH * TT];
// Er split: [r][64]
__device__ __nv_bfloat16 g_erh[TT * HH];
__device__ __nv_bfloat16 g_erl[TT * HH];
// W transposed+split: [n (0..191)][k (0..511)]
__device__ __nv_bfloat16 g_wth[192 * 512];
__device__ __nv_bfloat16 g_wtl[192 * 512];

__device__ __forceinline__ void pk(float x, float y, uint32_t& h, uint32_t& l) {
  __nv_bfloat16 hx = __float2bfloat16(x), hy = __float2bfloat16(y);
  float rx = x - __bfloat162float(hx), ry = y - __bfloat162float(hy);
  __nv_bfloat16 lx = __float2bfloat16(rx), ly = __float2bfloat16(ry);
  h = (uint32_t)__bfloat16_as_ushort(hx) |
      ((uint32_t)__bfloat16_as_ushort(hy) << 16);
  l = (uint32_t)__bfloat16_as_ushort(lx) |
      ((uint32_t)__bfloat16_as_ushort(ly) << 16);
}
__device__ __forceinline__ void pk1(float x, __nv_bfloat16& h,
                                    __nv_bfloat16& l) {
  h = __float2bfloat16(x);
  l = __float2bfloat16(x - __bfloat162float(h));
}

__device__ __forceinline__ void mma16(float* c, uint32_t a0, uint32_t a1,
                                      uint32_t a2, uint32_t a3, uint32_t b0,
                                      uint32_t b1) {
  asm volatile(
      "mma.sync.aligned.m16n8k16.row.col.f32.bf16.bf16.f32 "
      "{%0,%1,%2,%3}, {%4,%5,%6,%7}, {%8,%9}, {%0,%1,%2,%3};"
      : "+f"(c[0]), "+f"(c[1]), "+f"(c[2]), "+f"(c[3])
      : "r"(a0), "r"(a1), "r"(a2), "r"(a3), "r"(b0), "r"(b1));
}
__device__ __forceinline__ void mmax2(float* c, const uint32_t* ah,
                                      const uint32_t* al, uint32_t bh0,
                                      uint32_t bh1, uint32_t bl0,
                                      uint32_t bl1) {
  mma16(c, ah[0], ah[1], ah[2], ah[3], bl0, bl1);
  mma16(c, al[0], al[1], al[2], al[3], bh0, bh1);
  mma16(c, ah[0], ah[1], ah[2], ah[3], bh0, bh1);
}

// ---------------------------------------------------------------------------
// One-shot preps
// ---------------------------------------------------------------------------
__global__ __launch_bounds__(256) void prep_w(const float* __restrict__ Wq,
                                              const float* __restrict__ Wk,
                                              const float* __restrict__ Wv) {
  int idx = blockIdx.x * 256 + threadIdx.x;  // 192*512
  int n = idx >> 9, k = idx & 511;
  const float* Wm = n < 64 ? Wq : (n < 128 ? Wk : Wv);
  float v = Wm[(size_t)k * HH + (n & 63)];
  __nv_bfloat16 h, l;
  pk1(v, h, l);
  g_wth[idx] = h;
  g_wtl[idx] = l;
}

__global__ __launch_bounds__(256) void prep_er(const float* __restrict__ Er) {
  int idx = blockIdx.x * 256 + threadIdx.x;  // TT*HH
  __nv_bfloat16 h, l;
  pk1(Er[idx], h, l);
  g_erh[idx] = h;
  g_erl[idx] = l;
}

// ---------------------------------------------------------------------------
// QKV projection, bf16x2 m16n8k16. Epilogue writes split bf16 (V transposed).
// ---------------------------------------------------------------------------
#define WX 36
#define WW 36
#define QKV_WORDS (2 * 64 * WX + 2 * 192 * WW)
__global__ __launch_bounds__(256) void qkv_mma(const float* __restrict__ x) {
  extern __shared__ uint32_t qsm[];
  uint32_t* Xh = qsm;
  uint32_t* Xl = Xh + 64 * WX;
  uint32_t* WTh = Xl + 64 * WX;
  uint32_t* WTl = WTh + 192 * WW;
  int tid = threadIdx.x, w = tid >> 5, lane = tid & 31;
  int g = lane >> 2, tg = lane & 3;
  int row0 = blockIdx.x * 64;
  int mt = w & 3, nh = w >> 2;
  float acc[12][4] = {};

  for (int k0 = 0; k0 < CC; k0 += 64) {
    __syncthreads();
    for (int i = tid; i < 1024; i += 256) {  // X 64x64 floats, split
      int r = i >> 4, h4 = (i & 15) << 2;
      float4 v4 = *(const float4*)&x[(size_t)(row0 + r) * CC + k0 + h4];
      uint32_t h01, l01, h23, l23;
      pk(v4.x, v4.y, h01, l01);
      pk(v4.z, v4.w, h23, l23);
      int wc = r * WX + (h4 >> 1);
      *(uint2*)&Xh[wc] = make_uint2(h01, h23);
      *(uint2*)&Xl[wc] = make_uint2(l01, l23);
    }
    for (int i = tid; i < 1536; i += 256) {  // WT 192 rows x 32 words
      int n = i >> 3, w4 = (i & 7) << 2;
      int src = n * 256 + (k0 >> 1) + w4;
      *(uint4*)&WTh[n * WW + w4] = *(const uint4*)((const uint32_t*)g_wth + src);
      *(uint4*)&WTl[n * WW + w4] = *(const uint4*)((const uint32_t*)g_wtl + src);
    }
    __syncthreads();
    int r1 = 16 * mt + g, r2 = r1 + 8;
#pragma unroll
    for (int c4 = 0; c4 < 4; c4++) {
      int kw = 8 * c4;
      uint32_t ah[4], al[4];
      ah[0] = Xh[r1 * WX + kw + tg];
      ah[1] = Xh[r2 * WX + kw + tg];
      ah[2] = Xh[r1 * WX + kw + 4 + tg];
      ah[3] = Xh[r2 * WX + kw + 4 + tg];
      al[0] = Xl[r1 * WX + kw + tg];
      al[1] = Xl[r2 * WX + kw + tg];
      al[2] = Xl[r1 * WX + kw + 4 + tg];
      al[3] = Xl[r2 * WX + kw + 4 + tg];
#pragma unroll
      for (int v = 0; v < 12; v++) {
        int n = 8 * (12 * nh + v) + g;
        uint32_t bh0 = WTh[n * WW + kw + tg];
        uint32_t bh1 = WTh[n * WW + kw + 4 + tg];
        uint32_t bl0 = WTl[n * WW + kw + tg];
        uint32_t bl1 = WTl[n * WW + kw + 4 + tg];
        mmax2(acc[v], ah, al, bh0, bh1, bl0, bl1);
      }
    }
  }
  int r0g = row0 + 16 * mt + g;
#pragma unroll
  for (int v = 0; v < 12; v++) {
    int ncol = 8 * (12 * nh + v) + 2 * tg;
    int m = ncol >> 6, nn = ncol & 63;
    if (m < 2) {  // Q or K: split, packed-pair stores
      uint32_t* oh = (uint32_t*)(m == 0 ? g_qh : g_kh);
      uint32_t* ol = (uint32_t*)(m == 0 ? g_ql : g_kl);
      uint32_t h, l;
      pk(acc[v][0], acc[v][1], h, l);
      oh[(size_t)r0g * 32 + (nn >> 1)] = h;
      ol[(size_t)r0g * 32 + (nn >> 1)] = l;
      pk(acc[v][2], acc[v][3], h, l);
      oh[(size_t)(r0g + 8) * 32 + (nn >> 1)] = h;
      ol[(size_t)(r0g + 8) * 32 + (nn >> 1)] = l;
    } else {  // V: split + transpose -> [b*64+h][t]
      int bidx = r0g >> 11, t = r0g & 2047;
      size_t base = ((size_t)bidx * HH + nn) * TT + t;
      __nv_bfloat16 h, l;
      pk1(acc[v][0], h, l);
      g_vth[base] = h;
      g_vtl[base] = l;
      pk1(acc[v][1], h, l);
      g_vth[base + TT] = h;
      g_vtl[base + TT] = l;
      pk1(acc[v][2], h, l);
      g_vth[base + 8] = h;
      g_vtl[base + 8] = l;
      pk1(acc[v][3], h, l);
      g_vth[base + TT + 8] = h;
      g_vtl[base + TT + 8] = l;
    }
  }
}

// ---------------------------------------------------------------------------
// Fused attention, bf16x2, warp-specialized, all tile fills are pure copies.
// ---------------------------------------------------------------------------
#define WB 36  // words/row: Q,K,Qr,Er
#define WP 20  // words/row: P, Vt
#define PG 104
#define ATTN_WORDS                                                       \
  (2 * 64 * WB + 4 * 32 * WB + 2 * 96 * WB + 2 * 64 * WP + 2 * 64 * WP + \
   32 * PG + 3 * 64)

__global__ __launch_bounds__(256, 2) void attn_mma(
    const float* __restrict__ Er, float* __restrict__ out) {
  extern __shared__ uint32_t sm[];
  uint32_t* Qh = sm;
  uint32_t* Ql = Qh + 64 * WB;
  uint32_t* Kh = Ql + 64 * WB;
  uint32_t* Kl = Kh + 32 * WB;
  uint32_t* Qrh = Kl + 32 * WB;
  uint32_t* Qrl = Qrh + 32 * WB;
  uint32_t* Erh = Qrl + 32 * WB;
  uint32_t* Erl = Erh + 96 * WB;
  uint32_t* Vth = Erl + 96 * WB;  // [64 h][32 s]
  uint32_t* Vtl = Vth + 64 * WP;
  uint32_t* Ph = Vtl + 64 * WP;
  uint32_t* Pl = Ph + 64 * WP;
  float* Gs = (float*)(Pl + 64 * WP);  // 32 x PG
  float* ds = Gs + 32 * PG;
  float* as_ = ds + 64;
  float* lsm = as_ + 64;

  int tid = threadIdx.x, w = tid >> 5, lane = tid & 31;
  int g = lane >> 2, tg = lane & 3;
  int b = blockIdx.y;
  const uint4* QH4 = (const uint4*)g_qh + (size_t)b * TT * 8;  // 8 u4/row
  const uint4* QL4 = (const uint4*)g_ql + (size_t)b * TT * 8;
  const uint4* KH4 = (const uint4*)g_kh + (size_t)b * TT * 8;
  const uint4* KL4 = (const uint4*)g_kl + (size_t)b * TT * 8;
  const uint4* VTH4 = (const uint4*)g_vth + (size_t)b * HH * 256;  // 256 u4/h
  const uint4* VTL4 = (const uint4*)g_vtl + (size_t)b * HH * 256;
  const uint4* EH4 = (const uint4*)g_erh;
  const uint4* EL4 = (const uint4*)g_erl;

  int smt = w & 3, snh = w >> 2;

  for (int half = 0; half < 2; half++) {
    int t0 = half == 0 ? blockIdx.x * 64 : (TT - 64 - blockIdx.x * 64);
    __syncthreads();
    for (int i = tid; i < 1024; i += 256) {  // Q tile: 64 rows x 8 u4 x 2
      int hl = i >> 9, rem = i & 511;
      int r = rem >> 3, k4 = (rem & 7) << 2;
      const uint4* src = hl ? QL4 : QH4;
      uint32_t* dst = hl ? Ql : Qh;
      *(uint4*)&dst[r * WB + k4] = src[(t0 + r) * 8 + (k4 >> 2)];
    }
    __syncthreads();
    if (tid < 64) {
      const __nv_bfloat16* qh = (const __nv_bfloat16*)Qh + tid * 2 * WB;
      const __nv_bfloat16* ql = (const __nv_bfloat16*)Ql + tid * 2 * WB;
      const float* el = Er + (size_t)(TT - 1) * HH;
      float acc = 0.f;
#pragma unroll
      for (int h = 0; h < HH; h++)
        acc += (__bfloat162float(qh[h]) + __bfloat162float(ql[h])) * el[h];
      ds[tid] = acc;
    }

    float O[4][4] = {};
    float m_a = -1e30f, m_b = -1e30f, l_a = 0.f, l_b = 0.f;
    int niter = t0 / 32 + 2;

    for (int it = 0; it < niter; it++) {
      int s0 = it * 32;
      int rbase = t0 - s0 - 33;
      __syncthreads();
      // K + Qr: 32 rows x 8 u4 x 2 each = 1024 u4
      for (int i = tid; i < 1024; i += 256) {
        int which = i >> 9, rem = i & 511;  // 0=K, 1=Qr
        int hl = rem >> 8, rem2 = rem & 255;
        int r = rem2 >> 3, k4 = (rem2 & 7) << 2;
        uint4 val;
        uint32_t* dst;
        if (which == 0) {
          val = (hl ? KL4 : KH4)[(s0 + r) * 8 + (k4 >> 2)];
          dst = hl ? Kl : Kh;
        } else {
          int rq = s0 + 1 + r;
          if (rq > TT - 1) rq = TT - 1;  // clamped rows feed only masked slots
          val = (hl ? QL4 : QH4)[rq * 8 + (k4 >> 2)];
          dst = hl ? Qrl : Qrh;
        }
        *(uint4*)&dst[r * WB + k4] = val;
      }
      // Vt: 64 h x 4 u4 x 2 = 512 u4
      for (int i = tid; i < 512; i += 256) {
        int hl = i >> 8, rem = i & 255;
        int h = rem >> 2, t4 = (rem & 3) << 2;
        uint4 val = (hl ? VTL4 : VTH4)[h * 256 + (s0 >> 3) + (t4 >> 2)];
        uint32_t* dst = hl ? Vtl : Vth;
        *(uint4*)&dst[h * WP + t4] = val;
      }
      // Er band: 96 rows first iter, 32 after; x 8 u4 x 2
      {
        int nrows = it == 0 ? 96 : 32;
        for (int i = tid; i < nrows * 16; i += 256) {
          int xr = i >> 4, sub = i & 15;
          int hl = sub >> 3, k4 = (sub & 7) << 2;
          int r = rbase + xr;
          int slot = (r + 2112) % 96;
          int rc = r < 0 ? 0 : r;  // negative rows unused (masked)
          uint4 val = (hl ? EL4 : EH4)[rc * 8 + (k4 >> 2)];
          uint32_t* dst = hl ? Erl : Erh;
          *(uint4*)&dst[slot * WB + k4] = val;
        }
      }
      __syncthreads();

      float sf[4][4] = {};  // S fragments (warps 0-3)
      if (w < 4) {
        int r1 = 16 * w + g, r2 = r1 + 8;
#pragma unroll
        for (int c4 = 0; c4 < 4; c4++) {
          int kw = 8 * c4;
          uint32_t ah[4], al[4];
          ah[0] = Qh[r1 * WB + kw + tg];
          ah[1] = Qh[r2 * WB + kw + tg];
          ah[2] = Qh[r1 * WB + kw + 4 + tg];
          ah[3] = Qh[r2 * WB + kw + 4 + tg];
          al[0] = Ql[r1 * WB + kw + tg];
          al[1] = Ql[r2 * WB + kw + tg];
          al[2] = Ql[r1 * WB + kw + 4 + tg];
          al[3] = Ql[r2 * WB + kw + 4 + tg];
#pragma unroll
          for (int u = 0; u < 4; u++) {
            int br = 8 * u + g;
            uint32_t bh0 = Kh[br * WB + kw + tg];
            uint32_t bh1 = Kh[br * WB + kw + 4 + tg];
            uint32_t bl0 = Kl[br * WB + kw + tg];
            uint32_t bl1 = Kl[br * WB + kw + 4 + tg];
            mmax2(sf[u], ah, al, bh0, bh1, bl0, bl1);
          }
        }
      } else {
        int gw = w - 4;
        int mt2 = gw & 1, cg = gw >> 1;
        float gf[6][4] = {};
        int r1 = 16 * mt2 + g, r2 = r1 + 8;
#pragma unroll
        for (int c4 = 0; c4 < 4; c4++) {
          int kw = 8 * c4;
          uint32_t ah[4], al[4];
          ah[0] = Qrh[r1 * WB + kw + tg];
          ah[1] = Qrh[r2 * WB + kw + tg];
          ah[2] = Qrh[r1 * WB + kw + 4 + tg];
          ah[3] = Qrh[r2 * WB + kw + 4 + tg];
          al[0] = Qrl[r1 * WB + kw + tg];
          al[1] = Qrl[r2 * WB + kw + tg];
          al[2] = Qrl[r1 * WB + kw + 4 + tg];
          al[3] = Qrl[r2 * WB + kw + 4 + tg];
#pragma unroll
          for (int v = 0; v < 6; v++) {
            int br = 48 * cg + 8 * v + g;
            uint32_t bh0 = Erh[br * WB + kw + tg];
            uint32_t bh1 = Erh[br * WB + kw + 4 + tg];
            uint32_t bl0 = Erl[br * WB + kw + tg];
            uint32_t bl1 = Erl[br * WB + kw + 4 + tg];
            mmax2(gf[v], ah, al, bh0, bh1, bl0, bl1);
          }
        }
#pragma unroll
        for (int v = 0; v < 6; v++) {
          int n0 = 48 * cg + 8 * v + 2 * tg;
          *(float2*)&Gs[r1 * PG + n0] = make_float2(gf[v][0], gf[v][1]);
          *(float2*)&Gs[r2 * PG + n0] = make_float2(gf[v][2], gf[v][3]);
        }
      }
      __syncthreads();

      if (w < 4) {
        int ra = 16 * w + g, rb = ra + 8;
        int ta = t0 + ra, tb = t0 + rb;
        int baseA = rbase + ra + 31 + 2112;
        int baseB = rbase + rb + 31 + 2112;
        float va[8], vb[8];
        float dsa = ds[ra], dsb = ds[rb];
#pragma unroll
        for (int u = 0; u < 4; u++) {
#pragma unroll
          for (int e = 0; e < 2; e++) {
            int j = 8 * u + 2 * tg + e;
            int s = s0 + j;
            float adda = 0.f, addb = 0.f;
            if (s <= ta - 2)
              adda = Gs[j * PG + (baseA - j) % 96];
            else if (s == ta)
              adda = dsa;
            if (s <= tb - 2)
              addb = Gs[j * PG + (baseB - j) % 96];
            else if (s == tb)
              addb = dsb;
            float xa = SCALE * sf[u][e] + adda;
            float xb = SCALE * sf[u][2 + e] + addb;
            if (s > ta) xa = -1e30f;
            if (s > tb) xb = -1e30f;
            va[2 * u + e] = xa;
            vb[2 * u + e] = xb;
          }
        }
        float ma = va[0], mb = vb[0];
#pragma unroll
        for (int i = 1; i < 8; i++) {
          ma = fmaxf(ma, va[i]);
          mb = fmaxf(mb, vb[i]);
        }
        ma = fmaxf(ma, __shfl_xor_sync(0xffffffffu, ma, 1));
        ma = fmaxf(ma, __shfl_xor_sync(0xffffffffu, ma, 2));
        mb = fmaxf(mb, __shfl_xor_sync(0xffffffffu, mb, 1));
        mb = fmaxf(mb, __shfl_xor_sync(0xffffffffu, mb, 2));
        float mna = fmaxf(m_a, ma), mnb = fmaxf(m_b, mb);
        float ala = __expf(m_a - mna), alb = __expf(m_b - mnb);
        m_a = mna;
        m_b = mnb;
        float pa[8], pb[8];
        float rsa = 0.f, rsb = 0.f;
#pragma unroll
        for (int i = 0; i < 8; i++) {
          pa[i] = __expf(va[i] - mna);
          pb[i] = __expf(vb[i] - mnb);
          rsa += pa[i];
          rsb += pb[i];
        }
        rsa += __shfl_xor_sync(0xffffffffu, rsa, 1);
        rsa += __shfl_xor_sync(0xffffffffu, rsa, 2);
        rsb += __shfl_xor_sync(0xffffffffu, rsb, 1);
        rsb += __shfl_xor_sync(0xffffffffu, rsb, 2);
        l_a = ala * l_a + rsa;
        l_b = alb * l_b + rsb;
#pragma unroll
        for (int u = 0; u < 4; u++) {
          uint32_t h, l;
          pk(pa[2 * u], pa[2 * u + 1], h, l);
          Ph[ra * WP + 4 * u + tg] = h;
          Pl[ra * WP + 4 * u + tg] = l;
          pk(pb[2 * u], pb[2 * u + 1], h, l);
          Ph[rb * WP + 4 * u + tg] = h;
          Pl[rb * WP + 4 * u + tg] = l;
        }
        if (tg == 0) {
          as_[ra] = ala;
          as_[rb] = alb;
        }
      }
      __syncthreads();

      // O += P(64x32) @ V(32x64) via Vt, all warps
      {
        int r1 = 16 * smt + g, r2 = r1 + 8;
        float aa1 = as_[r1], aa2 = as_[r2];
#pragma unroll
        for (int v = 0; v < 4; v++) {
          O[v][0] *= aa1;
          O[v][1] *= aa1;
          O[v][2] *= aa2;
          O[v][3] *= aa2;
        }
#pragma unroll
        for (int c2 = 0; c2 < 2; c2++) {
          int kw = 8 * c2;
          uint32_t ah[4], al[4];
          ah[0] = Ph[r1 * WP + kw + tg];
          ah[1] = Ph[r2 * WP + kw + tg];
          ah[2] = Ph[r1 * WP + kw + 4 + tg];
          ah[3] = Ph[r2 * WP + kw + 4 + tg];
          al[0] = Pl[r1 * WP + kw + tg];
          al[1] = Pl[r2 * WP + kw + tg];
          al[2] = Pl[r1 * WP + kw + 4 + tg];
          al[3] = Pl[r2 * WP + kw + 4 + tg];
#pragma unroll
          for (int v = 0; v < 4; v++) {
            int n = 32 * snh + 8 * v + g;
            uint32_t bh0 = Vth[n * WP + kw + tg];
            uint32_t bh1 = Vth[n * WP + kw + 4 + tg];
            uint32_t bl0 = Vtl[n * WP + kw + tg];
            uint32_t bl1 = Vtl[n * WP + kw + 4 + tg];
            mmax2(O[v], ah, al, bh0, bh1, bl0, bl1);
          }
        }
      }
    }

    if (w < 4 && tg == 0) {
      lsm[16 * w + g] = l_a;
      lsm[16 * w + g + 8] = l_b;
    }
    __syncthreads();
    int r1 = 16 * smt + g, r2 = r1 + 8;
    float inv1 = 1.f / lsm[r1], inv2 = 1.f / lsm[r2];
#pragma unroll
    for (int v = 0; v < 4; v++) {
      int nc = 32 * snh + 8 * v + 2 * tg;
      *(float2*)&out[((size_t)b * TT + t0 + r1) * HH + nc] =
          make_float2(O[v][0] * inv1, O[v][1] * inv1);
      *(float2*)&out[((size_t)b * TT + t0 + r2) * HH + nc] =
          make_float2(O[v][2] * inv2, O[v][3] * inv2);
    }
  }
}

extern "C" void kernel_launch(void* const* d_in, const int* in_sizes, int n_in,
                              void* d_out, int out_size) {
  (void)in_sizes;
  (void)n_in;
  (void)out_size;
  const float* x = (const float*)d_in[0];
  const float* Wq = (const float*)d_in[1];
  const float* Wk = (const float*)d_in[2];
  const float* Wv = (const float*)d_in[3];
  const float* Er = (const float*)d_in[4];
  float* out = (float*)d_out;

  cudaFuncSetAttribute(qkv_mma, cudaFuncAttributeMaxDynamicSharedMemorySize,
                       QKV_WORDS * 4);
  cudaFuncSetAttribute(attn_mma, cudaFuncAttributeMaxDynamicSharedMemorySize,
                       ATTN_WORDS * 4);

  prep_w<<<dim3(192 * 512 / 256), 256>>>(Wq, Wk, Wv);
  prep_er<<<dim3(TT * HH / 256), 256>>>(Er);
  qkv_mma<<<dim3((BB * TT) / 64), 256, QKV_WORDS * 4>>>(x);
  attn_mma<<<dim3(TT / 128, BB), 256, ATTN_WORDS * 4>>>(Er, out);
}

// round 12
// speedup vs baseline: 1.8556x; 1.0038x over previous
#include <cuda_runtime.h>
#include <cuda_bf16.h>
#include <cstdint>

#define BB 16
#define TT 2048
#define CC 512
#define HH 64
#define SCALE 0.125f

// Q,K split bf16 (packed pairs), row-major [b*T + t][64]
__device__ __nv_bfloat16 g_qh[BB * TT * HH];
__device__ __nv_bfloat16 g_ql[BB * TT * HH];
__device__ __nv_bfloat16 g_kh[BB * TT * HH];
__device__ __nv_bfloat16 g_kl[BB * TT * HH];
// V split + transposed: [b*64 + h][t]
__device__ __nv_bfloat16 g_vth[BB * HH * TT];
__device__ __nv_bfloat16 g_vtl[BB * HH * TT];
// Er split: [r][64]
__device__ __nv_bfloat16 g_erh[TT * HH];
__device__ __nv_bfloat16 g_erl[TT * HH];
// W transposed+split: [n (0..191)][k (0..511)]
__device__ __nv_bfloat16 g_wth[192 * 512];
__device__ __nv_bfloat16 g_wtl[192 * 512];

__device__ __forceinline__ void pk(float x, float y, uint32_t& h, uint32_t& l) {
  __nv_bfloat16 hx = __float2bfloat16(x), hy = __float2bfloat16(y);
  float rx = x - __bfloat162float(hx), ry = y - __bfloat162float(hy);
  __nv_bfloat16 lx = __float2bfloat16(rx), ly = __float2bfloat16(ry);
  h = (uint32_t)__bfloat16_as_ushort(hx) |
      ((uint32_t)__bfloat16_as_ushort(hy) << 16);
  l = (uint32_t)__bfloat16_as_ushort(lx) |
      ((uint32_t)__bfloat16_as_ushort(ly) << 16);
}
__device__ __forceinline__ void pk1(float x, __nv_bfloat16& h,
                                    __nv_bfloat16& l) {
  h = __float2bfloat16(x);
  l = __float2bfloat16(x - __bfloat162float(h));
}

__device__ __forceinline__ void mma16(float* c, uint32_t a0, uint32_t a1,
                                      uint32_t a2, uint32_t a3, uint32_t b0,
                                      uint32_t b1) {
  asm volatile(
      "mma.sync.aligned.m16n8k16.row.col.f32.bf16.bf16.f32 "
      "{%0,%1,%2,%3}, {%4,%5,%6,%7}, {%8,%9}, {%0,%1,%2,%3};"
      : "+f"(c[0]), "+f"(c[1]), "+f"(c[2]), "+f"(c[3])
      : "r"(a0), "r"(a1), "r"(a2), "r"(a3), "r"(b0), "r"(b1));
}
__device__ __forceinline__ void mmax2(float* c, const uint32_t* ah,
                                      const uint32_t* al, uint32_t bh0,
                                      uint32_t bh1, uint32_t bl0,
                                      uint32_t bl1) {
  mma16(c, ah[0], ah[1], ah[2], ah[3], bl0, bl1);
  mma16(c, al[0], al[1], al[2], al[3], bh0, bh1);
  mma16(c, ah[0], ah[1], ah[2], ah[3], bh0, bh1);
}

// ldmatrix x4: 4 fragments in one instruction
__device__ __forceinline__ void ldm4(uint32_t& r0, uint32_t& r1, uint32_t& r2,
                                     uint32_t& r3, uint32_t addr) {
  asm volatile(
      "ldmatrix.sync.aligned.m8n8.x4.shared.b16 {%0,%1,%2,%3}, [%4];"
      : "=r"(r0), "=r"(r1), "=r"(r2), "=r"(r3)
      : "r"(addr));
}
__device__ __forceinline__ uint32_t sptr(const void* p) {
  return (uint32_t)__cvta_generic_to_shared(p);
}

// ---------------------------------------------------------------------------
// One-shot preps
// ---------------------------------------------------------------------------
__global__ __launch_bounds__(256) void prep_w(const float* __restrict__ Wq,
                                              const float* __restrict__ Wk,
                                              const float* __restrict__ Wv) {
  int idx = blockIdx.x * 256 + threadIdx.x;  // 192*512
  int n = idx >> 9, k = idx & 511;
  const float* Wm = n < 64 ? Wq : (n < 128 ? Wk : Wv);
  float v = Wm[(size_t)k * HH + (n & 63)];
  __nv_bfloat16 h, l;
  pk1(v, h, l);
  g_wth[idx] = h;
  g_wtl[idx] = l;
}

__global__ __launch_bounds__(256) void prep_er(const float* __restrict__ Er) {
  int idx = blockIdx.x * 256 + threadIdx.x;  // TT*HH
  __nv_bfloat16 h, l;
  pk1(Er[idx], h, l);
  g_erh[idx] = h;
  g_erl[idx] = l;
}

// ---------------------------------------------------------------------------
// QKV projection (unchanged from round 10).
// ---------------------------------------------------------------------------
#define WX 36
#define WW 36
#define QKV_WORDS (2 * 64 * WX + 2 * 192 * WW)
__global__ __launch_bounds__(256) void qkv_mma(const float* __restrict__ x) {
  extern __shared__ uint32_t qsm[];
  uint32_t* Xh = qsm;
  uint32_t* Xl = Xh + 64 * WX;
  uint32_t* WTh = Xl + 64 * WX;
  uint32_t* WTl = WTh + 192 * WW;
  int tid = threadIdx.x, w = tid >> 5, lane = tid & 31;
  int g = lane >> 2, tg = lane & 3;
  int row0 = blockIdx.x * 64;
  int mt = w & 3, nh = w >> 2;
  float acc[12][4] = {};

  for (int k0 = 0; k0 < CC; k0 += 64) {
    __syncthreads();
    for (int i = tid; i < 1024; i += 256) {  // X 64x64 floats, split
      int r = i >> 4, h4 = (i & 15) << 2;
      float4 v4 = *(const float4*)&x[(size_t)(row0 + r) * CC + k0 + h4];
      uint32_t h01, l01, h23, l23;
      pk(v4.x, v4.y, h01, l01);
      pk(v4.z, v4.w, h23, l23);
      int wc = r * WX + (h4 >> 1);
      *(uint2*)&Xh[wc] = make_uint2(h01, h23);
      *(uint2*)&Xl[wc] = make_uint2(l01, l23);
    }
    for (int i = tid; i < 1536; i += 256) {  // WT 192 rows x 32 words
      int n = i >> 3, w4 = (i & 7) << 2;
      int src = n * 256 + (k0 >> 1) + w4;
      *(uint4*)&WTh[n * WW + w4] = *(const uint4*)((const uint32_t*)g_wth + src);
      *(uint4*)&WTl[n * WW + w4] = *(const uint4*)((const uint32_t*)g_wtl + src);
    }
    __syncthreads();
    int r1 = 16 * mt + g, r2 = r1 + 8;
#pragma unroll
    for (int c4 = 0; c4 < 4; c4++) {
      int kw = 8 * c4;
      uint32_t ah[4], al[4];
      ah[0] = Xh[r1 * WX + kw + tg];
      ah[1] = Xh[r2 * WX + kw + tg];
      ah[2] = Xh[r1 * WX + kw + 4 + tg];
      ah[3] = Xh[r2 * WX + kw + 4 + tg];
      al[0] = Xl[r1 * WX + kw + tg];
      al[1] = Xl[r2 * WX + kw + tg];
      al[2] = Xl[r1 * WX + kw + 4 + tg];
      al[3] = Xl[r2 * WX + kw + 4 + tg];
#pragma unroll
      for (int v = 0; v < 12; v++) {
        int n = 8 * (12 * nh + v) + g;
        uint32_t bh0 = WTh[n * WW + kw + tg];
        uint32_t bh1 = WTh[n * WW + kw + 4 + tg];
        uint32_t bl0 = WTl[n * WW + kw + tg];
        uint32_t bl1 = WTl[n * WW + kw + 4 + tg];
        mmax2(acc[v], ah, al, bh0, bh1, bl0, bl1);
      }
    }
  }
  int r0g = row0 + 16 * mt + g;
#pragma unroll
  for (int v = 0; v < 12; v++) {
    int ncol = 8 * (12 * nh + v) + 2 * tg;
    int m = ncol >> 6, nn = ncol & 63;
    if (m < 2) {  // Q or K: split, packed-pair stores
      uint32_t* oh = (uint32_t*)(m == 0 ? g_qh : g_kh);
      uint32_t* ol = (uint32_t*)(m == 0 ? g_ql : g_kl);
      uint32_t h, l;
      pk(acc[v][0], acc[v][1], h, l);
      oh[(size_t)r0g * 32 + (nn >> 1)] = h;
      ol[(size_t)r0g * 32 + (nn >> 1)] = l;
      pk(acc[v][2], acc[v][3], h, l);
      oh[(size_t)(r0g + 8) * 32 + (nn >> 1)] = h;
      ol[(size_t)(r0g + 8) * 32 + (nn >> 1)] = l;
    } else {  // V: split + transpose -> [b*64+h][t]
      int bidx = r0g >> 11, t = r0g & 2047;
      size_t base = ((size_t)bidx * HH + nn) * TT + t;
      __nv_bfloat16 h, l;
      pk1(acc[v][0], h, l);
      g_vth[base] = h;
      g_vtl[base] = l;
      pk1(acc[v][1], h, l);
      g_vth[base + TT] = h;
      g_vtl[base + TT] = l;
      pk1(acc[v][2], h, l);
      g_vth[base + 8] = h;
      g_vtl[base + 8] = l;
      pk1(acc[v][3], h, l);
      g_vth[base + TT + 8] = h;
      g_vtl[base + TT + 8] = l;
    }
  }
}

// ---------------------------------------------------------------------------
// Fused attention: bf16x2, warp-specialized, ldmatrix fragment feeding.
// ---------------------------------------------------------------------------
#define WB 36  // words/row: Q,K,Qr,Er
#define WP 20  // words/row: P, Vt
#define PG 104
#define ATTN_WORDS                                                       \
  (2 * 64 * WB + 4 * 32 * WB + 2 * 96 * WB + 2 * 64 * WP + 2 * 64 * WP + \
   32 * PG + 3 * 64)

__global__ __launch_bounds__(256, 2) void attn_mma(
    const float* __restrict__ Er, float* __restrict__ out) {
  extern __shared__ uint32_t sm[];
  uint32_t* Qh = sm;
  uint32_t* Ql = Qh + 64 * WB;
  uint32_t* Kh = Ql + 64 * WB;
  uint32_t* Kl = Kh + 32 * WB;
  uint32_t* Qrh = Kl + 32 * WB;
  uint32_t* Qrl = Qrh + 32 * WB;
  uint32_t* Erh = Qrl + 32 * WB;
  uint32_t* Erl = Erh + 96 * WB;
  uint32_t* Vth = Erl + 96 * WB;  // [64 h][32 s]
  uint32_t* Vtl = Vth + 64 * WP;
  uint32_t* Ph = Vtl + 64 * WP;
  uint32_t* Pl = Ph + 64 * WP;
  float* Gs = (float*)(Pl + 64 * WP);  // 32 x PG
  float* ds = Gs + 32 * PG;
  float* as_ = ds + 64;
  float* lsm = as_ + 64;

  int tid = threadIdx.x, w = tid >> 5, lane = tid & 31;
  int g = lane >> 2, tg = lane & 3;
  int b = blockIdx.y;
  const uint4* QH4 = (const uint4*)g_qh + (size_t)b * TT * 8;
  const uint4* QL4 = (const uint4*)g_ql + (size_t)b * TT * 8;
  const uint4* KH4 = (const uint4*)g_kh + (size_t)b * TT * 8;
  const uint4* KL4 = (const uint4*)g_kl + (size_t)b * TT * 8;
  const uint4* VTH4 = (const uint4*)g_vth + (size_t)b * HH * 256;
  const uint4* VTL4 = (const uint4*)g_vtl + (size_t)b * HH * 256;
  const uint4* EH4 = (const uint4*)g_erh;
  const uint4* EL4 = (const uint4*)g_erl;

  int smt = w & 3, snh = w >> 2;

  // ldmatrix lane-address components (byte offsets)
  int lrowA = lane & 15;                               // A: row within 16
  int lcolA = ((lane >> 4) << 2);                      // A: +4 words for k+8
  int lrowB = (lane & 7) + ((lane >> 4) << 3);         // B: row within 16
  int lcolB = ((lane >> 3) & 1) << 2;                  // B: +4 words
  // S warp bases
  uint32_t aQh = sptr(Qh) + ((16 * w + lrowA) * WB + lcolA) * 4;
  uint32_t aQl = aQh + (uint32_t)(64 * WB * 4);
  uint32_t bKh = sptr(Kh) + (lrowB * WB + lcolB) * 4;
  uint32_t bKl = bKh + (uint32_t)(32 * WB * 4);
  // G warp bases
  int gw = w - 4, mt2 = gw & 1, cg = gw >> 1;
  uint32_t aRh = sptr(Qrh) + ((16 * mt2 + lrowA) * WB + lcolA) * 4;
  uint32_t aRl = aRh + (uint32_t)(32 * WB * 4);
  uint32_t bEh = sptr(Erh) + (((48 * cg) + lrowB) * WB + lcolB) * 4;
  uint32_t bEl = bEh + (uint32_t)(96 * WB * 4);
  // AV bases
  uint32_t aPh = sptr(Ph) + ((16 * smt + lrowA) * WP + lcolA) * 4;
  uint32_t aPl = aPh + (uint32_t)(64 * WP * 4);
  uint32_t bVh = sptr(Vth) + ((32 * snh + lrowB) * WP + lcolB) * 4;
  uint32_t bVl = bVh + (uint32_t)(64 * WP * 4);

  for (int half = 0; half < 2; half++) {
    int t0 = half == 0 ? blockIdx.x * 64 : (TT - 64 - blockIdx.x * 64);
    __syncthreads();
    for (int i = tid; i < 1024; i += 256) {  // Q tile: 64 rows x 8 u4 x 2
      int hl = i >> 9, rem = i & 511;
      int r = rem >> 3, k4 = (rem & 7) << 2;
      const uint4* src = hl ? QL4 : QH4;
      uint32_t* dst = hl ? Ql : Qh;
      *(uint4*)&dst[r * WB + k4] = src[(t0 + r) * 8 + (k4 >> 2)];
    }
    __syncthreads();
    if (tid < 64) {
      const __nv_bfloat16* qh = (const __nv_bfloat16*)Qh + tid * 2 * WB;
      const __nv_bfloat16* ql = (const __nv_bfloat16*)Ql + tid * 2 * WB;
      const float* el = Er + (size_t)(TT - 1) * HH;
      float acc = 0.f;
#pragma unroll
      for (int h = 0; h < HH; h++)
        acc += (__bfloat162float(qh[h]) + __bfloat162float(ql[h])) * el[h];
      ds[tid] = acc;
    }

    float O[4][4] = {};
    float m_a = -1e30f, m_b = -1e30f, l_a = 0.f, l_b = 0.f;
    int niter = t0 / 32 + 2;

    for (int it = 0; it < niter; it++) {
      int s0 = it * 32;
      int rbase = t0 - s0 - 33;
      __syncthreads();
      // K + Qr: 32 rows x 8 u4 x 2 each = 1024 u4
      for (int i = tid; i < 1024; i += 256) {
        int which = i >> 9, rem = i & 511;
        int hl = rem >> 8, rem2 = rem & 255;
        int r = rem2 >> 3, k4 = (rem2 & 7) << 2;
        uint4 val;
        uint32_t* dst;
        if (which == 0) {
          val = (hl ? KL4 : KH4)[(s0 + r) * 8 + (k4 >> 2)];
          dst = hl ? Kl : Kh;
        } else {
          int rq = s0 + 1 + r;
          if (rq > TT - 1) rq = TT - 1;  // clamped rows feed only masked slots
          val = (hl ? QL4 : QH4)[rq * 8 + (k4 >> 2)];
          dst = hl ? Qrl : Qrh;
        }
        *(uint4*)&dst[r * WB + k4] = val;
      }
      // Vt: 64 h x 4 u4 x 2 = 512 u4
      for (int i = tid; i < 512; i += 256) {
        int hl = i >> 8, rem = i & 255;
        int h = rem >> 2, t4 = (rem & 3) << 2;
        uint4 val = (hl ? VTL4 : VTH4)[h * 256 + (s0 >> 3) + (t4 >> 2)];
        uint32_t* dst = hl ? Vtl : Vth;
        *(uint4*)&dst[h * WP + t4] = val;
      }
      // Er band: 96 rows first iter, 32 after; x 8 u4 x 2
      {
        int nrows = it == 0 ? 96 : 32;
        for (int i = tid; i < nrows * 16; i += 256) {
          int xr = i >> 4, sub = i & 15;
          int hl = sub >> 3, k4 = (sub & 7) << 2;
          int r = rbase + xr;
          int slot = (r + 2112) % 96;
          int rc = r < 0 ? 0 : r;  // negative rows unused (masked)
          uint4 val = (hl ? EL4 : EH4)[rc * 8 + (k4 >> 2)];
          uint32_t* dst = hl ? Erl : Erh;
          *(uint4*)&dst[slot * WB + k4] = val;
        }
      }
      __syncthreads();

      float sf[4][4] = {};  // S fragments (warps 0-3)
      if (w < 4) {
#pragma unroll
        for (int c4 = 0; c4 < 4; c4++) {
          uint32_t kof = 32 * c4;  // 8 words
          uint32_t ah[4], al[4], bh[8], bl[8];
          ldm4(ah[0], ah[1], ah[2], ah[3], aQh + kof);
          ldm4(al[0], al[1], al[2], al[3], aQl + kof);
          ldm4(bh[0], bh[1], bh[2], bh[3], bKh + kof);
          ldm4(bh[4], bh[5], bh[6], bh[7], bKh + 16 * WB * 4 + kof);
          ldm4(bl[0], bl[1], bl[2], bl[3], bKl + kof);
          ldm4(bl[4], bl[5], bl[6], bl[7], bKl + 16 * WB * 4 + kof);
#pragma unroll
          for (int u = 0; u < 4; u++)
            mmax2(sf[u], ah, al, bh[2 * u], bh[2 * u + 1], bl[2 * u],
                  bl[2 * u + 1]);
        }
      } else {
        float gf[6][4] = {};
#pragma unroll
        for (int c4 = 0; c4 < 4; c4++) {
          uint32_t kof = 32 * c4;
          uint32_t ah[4], al[4], bh[12], bl[12];
          ldm4(ah[0], ah[1], ah[2], ah[3], aRh + kof);
          ldm4(al[0], al[1], al[2], al[3], aRl + kof);
          ldm4(bh[0], bh[1], bh[2], bh[3], bEh + kof);
          ldm4(bh[4], bh[5], bh[6], bh[7], bEh + 16 * WB * 4 + kof);
          ldm4(bh[8], bh[9], bh[10], bh[11], bEh + 32 * WB * 4 + kof);
          ldm4(bl[0], bl[1], bl[2], bl[3], bEl + kof);
          ldm4(bl[4], bl[5], bl[6], bl[7], bEl + 16 * WB * 4 + kof);
          ldm4(bl[8], bl[9], bl[10], bl[11], bEl + 32 * WB * 4 + kof);
#pragma unroll
          for (int v = 0; v < 6; v++)
            mmax2(gf[v], ah, al, bh[2 * v], bh[2 * v + 1], bl[2 * v],
                  bl[2 * v + 1]);
        }
        int r1 = 16 * mt2 + g, r2 = r1 + 8;
#pragma unroll
        for (int v = 0; v < 6; v++) {
          int n0 = 48 * cg + 8 * v + 2 * tg;
          *(float2*)&Gs[r1 * PG + n0] = make_float2(gf[v][0], gf[v][1]);
          *(float2*)&Gs[r2 * PG + n0] = make_float2(gf[v][2], gf[v][3]);
        }
      }
      __syncthreads();

      if (w < 4) {
        int ra = 16 * w + g, rb = ra + 8;
        int ta = t0 + ra, tb = t0 + rb;
        int baseA = rbase + ra + 31 + 2112;
        int baseB = rbase + rb + 31 + 2112;
        float va[8], vb[8];
        float dsa = ds[ra], dsb = ds[rb];
#pragma unroll
        for (int u = 0; u < 4; u++) {
#pragma unroll
          for (int e = 0; e < 2; e++) {
            int j = 8 * u + 2 * tg + e;
            int s = s0 + j;
            float adda = 0.f, addb = 0.f;
            if (s <= ta - 2)
              adda = Gs[j * PG + (baseA - j) % 96];
            else if (s == ta)
              adda = dsa;
            if (s <= tb - 2)
              addb = Gs[j * PG + (baseB - j) % 96];
            else if (s == tb)
              addb = dsb;
            float xa = SCALE * sf[u][e] + adda;
            float xb = SCALE * sf[u][2 + e] + addb;
            if (s > ta) xa = -1e30f;
            if (s > tb) xb = -1e30f;
            va[2 * u + e] = xa;
            vb[2 * u + e] = xb;
          }
        }
        float ma = va[0], mb = vb[0];
#pragma unroll
        for (int i = 1; i < 8; i++) {
          ma = fmaxf(ma, va[i]);
          mb = fmaxf(mb, vb[i]);
        }
        ma = fmaxf(ma, __shfl_xor_sync(0xffffffffu, ma, 1));
        ma = fmaxf(ma, __shfl_xor_sync(0xffffffffu, ma, 2));
        mb = fmaxf(mb, __shfl_xor_sync(0xffffffffu, mb, 1));
        mb = fmaxf(mb, __shfl_xor_sync(0xffffffffu, mb, 2));
        float mna = fmaxf(m_a, ma), mnb = fmaxf(m_b, mb);
        float ala = __expf(m_a - mna), alb = __expf(m_b - mnb);
        m_a = mna;
        m_b = mnb;
        float pa[8], pb[8];
        float rsa = 0.f, rsb = 0.f;
#pragma unroll
        for (int i = 0; i < 8; i++) {
          pa[i] = __expf(va[i] - mna);
          pb[i] = __expf(vb[i] - mnb);
          rsa += pa[i];
          rsb += pb[i];
        }
        rsa += __shfl_xor_sync(0xffffffffu, rsa, 1);
        rsa += __shfl_xor_sync(0xffffffffu, rsa, 2);
        rsb += __shfl_xor_sync(0xffffffffu, rsb, 1);
        rsb += __shfl_xor_sync(0xffffffffu, rsb, 2);
        l_a = ala * l_a + rsa;
        l_b = alb * l_b + rsb;
#pragma unroll
        for (int u = 0; u < 4; u++) {
          uint32_t h, l;
          pk(pa[2 * u], pa[2 * u + 1], h, l);
          Ph[ra * WP + 4 * u + tg] = h;
          Pl[ra * WP + 4 * u + tg] = l;
          pk(pb[2 * u], pb[2 * u + 1], h, l);
          Ph[rb * WP + 4 * u + tg] = h;
          Pl[rb * WP + 4 * u + tg] = l;
        }
        if (tg == 0) {
          as_[ra] = ala;
          as_[rb] = alb;
        }
      }
      __syncthreads();

      // O += P(64x32) @ V(32x64) via Vt, all warps
      {
        int r1 = 16 * smt + g, r2 = r1 + 8;
        float aa1 = as_[r1], aa2 = as_[r2];
#pragma unroll
        for (int v = 0; v < 4; v++) {
          O[v][0] *= aa1;
          O[v][1] *= aa1;
          O[v][2] *= aa2;
          O[v][3] *= aa2;
        }
#pragma unroll
        for (int c2 = 0; c2 < 2; c2++) {
          uint32_t kof = 32 * c2;
          uint32_t ah[4], al[4], bh[8], bl[8];
          ldm4(ah[0], ah[1], ah[2], ah[3], aPh + kof);
          ldm4(al[0], al[1], al[2], al[3], aPl + kof);
          ldm4(bh[0], bh[1], bh[2], bh[3], bVh + kof);
          ldm4(bh[4], bh[5], bh[6], bh[7], bVh + 16 * WP * 4 + kof);
          ldm4(bl[0], bl[1], bl[2], bl[3], bVl + kof);
          ldm4(bl[4], bl[5], bl[6], bl[7], bVl + 16 * WP * 4 + kof);
#pragma unroll
          for (int v = 0; v < 4; v++)
            mmax2(O[v], ah, al, bh[2 * v], bh[2 * v + 1], bl[2 * v],
                  bl[2 * v + 1]);
        }
      }
    }

    if (w < 4 && tg == 0) {
      lsm[16 * w + g] = l_a;
      lsm[16 * w + g + 8] = l_b;
    }
    __syncthreads();
    int r1 = 16 * smt + g, r2 = r1 + 8;
    float inv1 = 1.f / lsm[r1], inv2 = 1.f / lsm[r2];
#pragma unroll
    for (int v = 0; v < 4; v++) {
      int nc = 32 * snh + 8 * v + 2 * tg;
      *(float2*)&out[((size_t)b * TT + t0 + r1) * HH + nc] =
          make_float2(O[v][0] * inv1, O[v][1] * inv1);
      *(float2*)&out[((size_t)b * TT + t0 + r2) * HH + nc] =
          make_float2(O[v][2] * inv2, O[v][3] * inv2);
    }
  }
}

extern "C" void kernel_launch(void* const* d_in, const int* in_sizes, int n_in,
                              void* d_out, int out_size) {
  (void)in_sizes;
  (void)n_in;
  (void)out_size;
  const float* x = (const float*)d_in[0];
  const float* Wq = (const float*)d_in[1];
  const float* Wk = (const float*)d_in[2];
  const float* Wv = (const float*)d_in[3];
  const float* Er = (const float*)d_in[4];
  float* out = (float*)d_out;

  cudaFuncSetAttribute(qkv_mma, cudaFuncAttributeMaxDynamicSharedMemorySize,
                       QKV_WORDS * 4);
  cudaFuncSetAttribute(attn_mma, cudaFuncAttributeMaxDynamicSharedMemorySize,
                       ATTN_WORDS * 4);

  prep_w<<<dim3(192 * 512 / 256), 256>>>(Wq, Wk, Wv);
  prep_er<<<dim3(TT * HH / 256), 256>>>(Er);
  qkv_mma<<<dim3((BB * TT) / 64), 256, QKV_WORDS * 4>>>(x);
  attn_mma<<<dim3(TT / 128, BB), 256, ATTN_WORDS * 4>>>(Er, out);
}